// round 3
// baseline (speedup 1.0000x reference)
#include <cuda_runtime.h>
#include <cuda_bf16.h>
#include <math.h>

// ---------------------------------------------------------------------------
// Problem constants
// ---------------------------------------------------------------------------
#define NTOK   8192          // B*T = 4*2048
#define HS     1024
#define DKTOT  512
#define DVTOT  1024
#define NH     4
#define DK     128           // dk per head
#define DV     256           // dv per head
#define CH     64            // chunk
#define NCHUNK 32            // T / CH
#define RLOW   16
#define IMLP   2816
#define EPS    1e-6f
#define GLN    16.0f         // GATE_LOGIT_NORMALIZER

// ---------------------------------------------------------------------------
// Scratch (static device memory; no allocations allowed).  ~270 MB.
// Reuse map (phases strictly ordered by stream order):
//   h    -> n   (mlp-norm out)
//   v    -> og  (gated attn out)
//   gout -> x2  (residual-1)
//   gla  -> tmp (Wo output)
// ---------------------------------------------------------------------------
#define OFF_H     0ull                       //  8M floats
#define OFF_Q     (OFF_H    + 8388608ull)    //  4M
#define OFF_K     (OFF_Q    + 4194304ull)    //  4M
#define OFF_V     (OFF_K    + 4194304ull)    //  8M
#define OFF_GOUT  (OFF_V    + 8388608ull)    //  8M
#define OFF_GLOW  (OFF_GOUT + 8388608ull)    //  128K
#define OFF_GLOG  (OFF_GLOW + 131072ull)     //  4M
#define OFF_GLA   (OFF_GLOG + 4194304ull)    //  8M
#define OFF_UP    (OFF_GLA  + 8388608ull)    //  23M (8192*2816)
#define SCRATCH_FLOATS (OFF_UP + 23068672ull)

__device__ float g_scratch[SCRATCH_FLOATS];

// ---------------------------------------------------------------------------
// Utility
// ---------------------------------------------------------------------------
__device__ __forceinline__ float sigmoidf_(float x) {
    return 1.0f / (1.0f + expf(-x));
}
__device__ __forceinline__ float logsigmoidf_(float x) {
    return fminf(x, 0.0f) - log1pf(expf(-fabsf(x)));
}

__device__ __forceinline__ float block_reduce_sum_256(float v, float* red8) {
    #pragma unroll
    for (int o = 16; o > 0; o >>= 1) v += __shfl_xor_sync(0xffffffffu, v, o);
    if ((threadIdx.x & 31) == 0) red8[threadIdx.x >> 5] = v;
    __syncthreads();
    float s;
    if (threadIdx.x < 8) {
        s = red8[threadIdx.x];
        #pragma unroll
        for (int o = 4; o > 0; o >>= 1) s += __shfl_xor_sync(0xffu, s, o);
        if (threadIdx.x == 0) red8[0] = s;
    }
    __syncthreads();
    return red8[0];
}

// ---------------------------------------------------------------------------
// RMSNorm over 1024-wide rows.  grid = NTOK, block = 256
// ---------------------------------------------------------------------------
__global__ __launch_bounds__(256) void rmsnorm1024_kernel(
    const float* __restrict__ x, const float* __restrict__ w,
    float* __restrict__ y)
{
    __shared__ float red8[8];
    const size_t row = blockIdx.x;
    const float4* xr = (const float4*)(x + row * (size_t)HS);
    float4 v = xr[threadIdx.x];
    float ss = v.x * v.x + v.y * v.y + v.z * v.z + v.w * v.w;
    float tot = block_reduce_sum_256(ss, red8);
    float r = rsqrtf(tot / (float)HS + EPS);
    const float4* wr = (const float4*)w;
    float4 wv = wr[threadIdx.x];
    float4 o;
    o.x = v.x * r * wv.x; o.y = v.y * r * wv.y;
    o.z = v.z * r * wv.z; o.w = v.w * r * wv.w;
    ((float4*)(y + row * (size_t)HS))[threadIdx.x] = o;
}

// ---------------------------------------------------------------------------
// SGEMM: C[M,N] = A[M,K]*B[K,N] (+ epilogue), row-major, M%128==0, N%128==0.
// 128x128 tile, 256 threads, 8x8 per-thread microtile.
// EPI: 0 = none, 1 = C = acc + E (residual), 2 = C = silu(acc) * E (in-place ok)
// ---------------------------------------------------------------------------
template <int EPI>
__global__ __launch_bounds__(256) void sgemm128_kernel(
    const float* __restrict__ A, const float* __restrict__ B,
    float* __restrict__ C, const float* __restrict__ E,
    int M, int N, int K)
{
    __shared__ float As[8][128];
    __shared__ float Bs[8][128];

    const int tid = threadIdx.x;
    const int m0 = blockIdx.y * 128;
    const int n0 = blockIdx.x * 128;

    const int ty = tid >> 4;       // 0..15
    const int tx = tid & 15;       // 0..15

    const int arow = tid >> 1;         // 0..127
    const int acol = (tid & 1) * 4;    // 0 or 4
    const int brow = tid >> 5;         // 0..7
    const int bcol = (tid & 31) * 4;   // 0..124

    const float* Aptr = A + (size_t)(m0 + arow) * K + acol;
    const float* Bptr = B + (size_t)brow * N + n0 + bcol;

    float acc[8][8];
    #pragma unroll
    for (int i = 0; i < 8; i++)
        #pragma unroll
        for (int j = 0; j < 8; j++) acc[i][j] = 0.0f;

    for (int kt = 0; kt < K; kt += 8) {
        float4 a4 = *(const float4*)(Aptr + kt);
        float4 b4 = *(const float4*)(Bptr + (size_t)kt * N);

        __syncthreads();
        As[acol + 0][arow] = a4.x;
        As[acol + 1][arow] = a4.y;
        As[acol + 2][arow] = a4.z;
        As[acol + 3][arow] = a4.w;
        *(float4*)&Bs[brow][bcol] = b4;
        __syncthreads();

        #pragma unroll
        for (int kk = 0; kk < 8; kk++) {
            float af[8], bf[8];
            *(float4*)(af)     = *(const float4*)&As[kk][ty * 8];
            *(float4*)(af + 4) = *(const float4*)&As[kk][ty * 8 + 4];
            *(float4*)(bf)     = *(const float4*)&Bs[kk][tx * 8];
            *(float4*)(bf + 4) = *(const float4*)&Bs[kk][tx * 8 + 4];
            #pragma unroll
            for (int i = 0; i < 8; i++)
                #pragma unroll
                for (int j = 0; j < 8; j++)
                    acc[i][j] = fmaf(af[i], bf[j], acc[i][j]);
        }
    }

    #pragma unroll
    for (int i = 0; i < 8; i++) {
        size_t roff = (size_t)(m0 + ty * 8 + i) * N + n0 + tx * 8;
        float* Crow = C + roff;
        float out[8];
        if (EPI == 1) {
            const float* Erow = E + roff;
            float4 e0 = ((const float4*)Erow)[0];
            float4 e1 = ((const float4*)Erow)[1];
            out[0] = acc[i][0] + e0.x; out[1] = acc[i][1] + e0.y;
            out[2] = acc[i][2] + e0.z; out[3] = acc[i][3] + e0.w;
            out[4] = acc[i][4] + e1.x; out[5] = acc[i][5] + e1.y;
            out[6] = acc[i][6] + e1.z; out[7] = acc[i][7] + e1.w;
        } else if (EPI == 2) {
            const float* Erow = E + roff;
            float4 e0 = ((const float4*)Erow)[0];
            float4 e1 = ((const float4*)Erow)[1];
            out[0] = acc[i][0] * sigmoidf_(acc[i][0]) * e0.x;
            out[1] = acc[i][1] * sigmoidf_(acc[i][1]) * e0.y;
            out[2] = acc[i][2] * sigmoidf_(acc[i][2]) * e0.z;
            out[3] = acc[i][3] * sigmoidf_(acc[i][3]) * e0.w;
            out[4] = acc[i][4] * sigmoidf_(acc[i][4]) * e1.x;
            out[5] = acc[i][5] * sigmoidf_(acc[i][5]) * e1.y;
            out[6] = acc[i][6] * sigmoidf_(acc[i][6]) * e1.z;
            out[7] = acc[i][7] * sigmoidf_(acc[i][7]) * e1.w;
        } else {
            #pragma unroll
            for (int j = 0; j < 8; j++) out[j] = acc[i][j];
        }
        ((float4*)Crow)[0] = make_float4(out[0], out[1], out[2], out[3]);
        ((float4*)Crow)[1] = make_float4(out[4], out[5], out[6], out[7]);
    }
}

// ---------------------------------------------------------------------------
// low-rank gate: glow[m,r] = sum_k h[m,k]*Wgk1[k,r]   (M=8192, K=1024, R=16)
// ---------------------------------------------------------------------------
__global__ __launch_bounds__(256) void glow_kernel(
    const float* __restrict__ h, const float* __restrict__ Wgk1,
    float* __restrict__ glow)
{
    int idx = blockIdx.x * 256 + threadIdx.x;
    int m = idx >> 4;
    int r = idx & 15;
    const float* hr = h + (size_t)m * HS;
    float acc = 0.0f;
    #pragma unroll 8
    for (int k = 0; k < HS; k++)
        acc = fmaf(hr[k], Wgk1[(size_t)k * RLOW + r], acc);
    glow[idx] = acc;
}

// glog[m,n] = logsigmoid(glow[m,:]@Wgk2[:,n] + bgk2[n]) / 16
__global__ __launch_bounds__(256) void glog_kernel(
    const float* __restrict__ glow, const float* __restrict__ Wgk2,
    const float* __restrict__ bgk2, float* __restrict__ glog)
{
    int idx = blockIdx.x * 256 + threadIdx.x;
    int m = idx >> 9;
    int n = idx & 511;
    const float* gr = glow + (size_t)m * RLOW;
    float acc = bgk2[n];
    #pragma unroll
    for (int r = 0; r < RLOW; r++)
        acc = fmaf(gr[r], Wgk2[(size_t)r * DKTOT + n], acc);
    glog[idx] = logsigmoidf_(acc) / GLN;
}

// ---------------------------------------------------------------------------
// GLA chunked attention.  grid = (4 dv-blocks, NH, B), block = 256.
// S[128 x 64] persistent in shared memory across 32 chunks.
// ---------------------------------------------------------------------------
#define DKP 129
#define PE  65
#define GLA_SMEM_FLOATS (128*PE + 3*CH*DKP + 2*CH*PE)
#define GLA_SMEM_BYTES  (GLA_SMEM_FLOATS * 4)

extern __shared__ float gla_sm[];

__global__ __launch_bounds__(256) void gla_attn_kernel(
    const float* __restrict__ q, const float* __restrict__ k,
    const float* __restrict__ v, const float* __restrict__ g,
    float* __restrict__ out)
{
    const int ev = blockIdx.x;
    const int h  = blockIdx.y;
    const int b  = blockIdx.z;
    const int tid = threadIdx.x;

    float* S   = gla_sm;                    // [128][PE]
    float* qe  = S  + 128 * PE;             // [64][DKP]
    float* kd  = qe + CH * DKP;             // [64][DKP]
    float* bc  = kd + CH * DKP;             // [64][DKP]
    float* vs  = bc + CH * DKP;             // [64][PE]
    float* Am  = vs + CH * PE;              // [64][PE]

    for (int i = tid; i < 128 * PE; i += 256) S[i] = 0.0f;

    const float scale = rsqrtf((float)DK);
    const size_t baseqk = ((size_t)b * 2048) * DKTOT + (size_t)h * DK;
    const size_t basev  = ((size_t)b * 2048) * DVTOT + (size_t)h * DV + (size_t)ev * 64;
    const float* qb = q + baseqk;
    const float* kb = k + baseqk;
    const float* gb = g + baseqk;
    const float* vb = v + basev;
    float* ob = out + basev;

    for (int n = 0; n < NCHUNK; n++) {
        const int t0 = n * CH;
        __syncthreads();

        if (tid < DK) {
            float run = 0.0f;
            #pragma unroll 8
            for (int c = 0; c < CH; c++) {
                run += gb[(size_t)(t0 + c) * DKTOT + tid];
                bc[c * DKP + tid] = run;
            }
        }
        for (int i = tid; i < CH * 64; i += 256) {
            int c = i >> 6, e = i & 63;
            vs[c * PE + e] = vb[(size_t)(t0 + c) * DVTOT + e];
        }
        __syncthreads();

        for (int i = tid; i < CH * DK; i += 256) {
            int c = i >> 7, d = i & 127;
            float bv = bc[c * DKP + d];
            size_t gi = (size_t)(t0 + c) * DKTOT + d;
            qe[c * DKP + d] = qb[gi] * expf(bv) * scale;
            kd[c * DKP + d] = kb[gi] * expf(-bv);
        }
        __syncthreads();

        // A[c,s] = qe[c,:].kd[s,:]  (masked c>=s)
        {
            const int tc = (tid >> 4) * 4;
            const int ts = (tid & 15) * 4;
            float acc[4][4];
            #pragma unroll
            for (int i = 0; i < 4; i++)
                #pragma unroll
                for (int j = 0; j < 4; j++) acc[i][j] = 0.0f;
            for (int d = 0; d < DK; d++) {
                float a0 = qe[(tc + 0) * DKP + d];
                float a1 = qe[(tc + 1) * DKP + d];
                float a2 = qe[(tc + 2) * DKP + d];
                float a3 = qe[(tc + 3) * DKP + d];
                float b0 = kd[(ts + 0) * DKP + d];
                float b1 = kd[(ts + 1) * DKP + d];
                float b2 = kd[(ts + 2) * DKP + d];
                float b3 = kd[(ts + 3) * DKP + d];
                acc[0][0] = fmaf(a0, b0, acc[0][0]); acc[0][1] = fmaf(a0, b1, acc[0][1]);
                acc[0][2] = fmaf(a0, b2, acc[0][2]); acc[0][3] = fmaf(a0, b3, acc[0][3]);
                acc[1][0] = fmaf(a1, b0, acc[1][0]); acc[1][1] = fmaf(a1, b1, acc[1][1]);
                acc[1][2] = fmaf(a1, b2, acc[1][2]); acc[1][3] = fmaf(a1, b3, acc[1][3]);
                acc[2][0] = fmaf(a2, b0, acc[2][0]); acc[2][1] = fmaf(a2, b1, acc[2][1]);
                acc[2][2] = fmaf(a2, b2, acc[2][2]); acc[2][3] = fmaf(a2, b3, acc[2][3]);
                acc[3][0] = fmaf(a3, b0, acc[3][0]); acc[3][1] = fmaf(a3, b1, acc[3][1]);
                acc[3][2] = fmaf(a3, b2, acc[3][2]); acc[3][3] = fmaf(a3, b3, acc[3][3]);
            }
            #pragma unroll
            for (int i = 0; i < 4; i++)
                #pragma unroll
                for (int j = 0; j < 4; j++)
                    Am[(tc + i) * PE + ts + j] =
                        (tc + i >= ts + j) ? acc[i][j] : 0.0f;
        }
        __syncthreads();

        // o = A @ v + qe @ S
        {
            const int tc = (tid >> 4) * 4;
            const int te = (tid & 15) * 4;
            float acc[4][4];
            #pragma unroll
            for (int i = 0; i < 4; i++)
                #pragma unroll
                for (int j = 0; j < 4; j++) acc[i][j] = 0.0f;
            for (int s = 0; s < CH; s++) {
                float a0 = Am[(tc + 0) * PE + s];
                float a1 = Am[(tc + 1) * PE + s];
                float a2 = Am[(tc + 2) * PE + s];
                float a3 = Am[(tc + 3) * PE + s];
                float v0 = vs[s * PE + te + 0];
                float v1 = vs[s * PE + te + 1];
                float v2 = vs[s * PE + te + 2];
                float v3 = vs[s * PE + te + 3];
                acc[0][0] = fmaf(a0, v0, acc[0][0]); acc[0][1] = fmaf(a0, v1, acc[0][1]);
                acc[0][2] = fmaf(a0, v2, acc[0][2]); acc[0][3] = fmaf(a0, v3, acc[0][3]);
                acc[1][0] = fmaf(a1, v0, acc[1][0]); acc[1][1] = fmaf(a1, v1, acc[1][1]);
                acc[1][2] = fmaf(a1, v2, acc[1][2]); acc[1][3] = fmaf(a1, v3, acc[1][3]);
                acc[2][0] = fmaf(a2, v0, acc[2][0]); acc[2][1] = fmaf(a2, v1, acc[2][1]);
                acc[2][2] = fmaf(a2, v2, acc[2][2]); acc[2][3] = fmaf(a2, v3, acc[2][3]);
                acc[3][0] = fmaf(a3, v0, acc[3][0]); acc[3][1] = fmaf(a3, v1, acc[3][1]);
                acc[3][2] = fmaf(a3, v2, acc[3][2]); acc[3][3] = fmaf(a3, v3, acc[3][3]);
            }
            for (int d = 0; d < DK; d++) {
                float a0 = qe[(tc + 0) * DKP + d];
                float a1 = qe[(tc + 1) * DKP + d];
                float a2 = qe[(tc + 2) * DKP + d];
                float a3 = qe[(tc + 3) * DKP + d];
                float s0 = S[d * PE + te + 0];
                float s1 = S[d * PE + te + 1];
                float s2 = S[d * PE + te + 2];
                float s3 = S[d * PE + te + 3];
                acc[0][0] = fmaf(a0, s0, acc[0][0]); acc[0][1] = fmaf(a0, s1, acc[0][1]);
                acc[0][2] = fmaf(a0, s2, acc[0][2]); acc[0][3] = fmaf(a0, s3, acc[0][3]);
                acc[1][0] = fmaf(a1, s0, acc[1][0]); acc[1][1] = fmaf(a1, s1, acc[1][1]);
                acc[1][2] = fmaf(a1, s2, acc[1][2]); acc[1][3] = fmaf(a1, s3, acc[1][3]);
                acc[2][0] = fmaf(a2, s0, acc[2][0]); acc[2][1] = fmaf(a2, s1, acc[2][1]);
                acc[2][2] = fmaf(a2, s2, acc[2][2]); acc[2][3] = fmaf(a2, s3, acc[2][3]);
                acc[3][0] = fmaf(a3, s0, acc[3][0]); acc[3][1] = fmaf(a3, s1, acc[3][1]);
                acc[3][2] = fmaf(a3, s2, acc[3][2]); acc[3][3] = fmaf(a3, s3, acc[3][3]);
            }
            #pragma unroll
            for (int i = 0; i < 4; i++)
                #pragma unroll
                for (int j = 0; j < 4; j++)
                    ob[(size_t)(t0 + tc + i) * DVTOT + te + j] = acc[i][j];
        }
        __syncthreads();

        // S = exp(blast) * (S + kd^T @ v)
        {
            const int td = (tid & 31) * 4;
            const int te = (tid >> 5) * 8;
            float ex[4];
            #pragma unroll
            for (int i = 0; i < 4; i++) ex[i] = expf(bc[63 * DKP + td + i]);
            float acc[4][8];
            #pragma unroll
            for (int i = 0; i < 4; i++)
                #pragma unroll
                for (int j = 0; j < 8; j++)
                    acc[i][j] = S[(td + i) * PE + te + j];
            for (int c = 0; c < CH; c++) {
                float k0 = kd[c * DKP + td + 0];
                float k1 = kd[c * DKP + td + 1];
                float k2 = kd[c * DKP + td + 2];
                float k3 = kd[c * DKP + td + 3];
                #pragma unroll
                for (int j = 0; j < 8; j++) {
                    float vv = vs[c * PE + te + j];
                    acc[0][j] = fmaf(k0, vv, acc[0][j]);
                    acc[1][j] = fmaf(k1, vv, acc[1][j]);
                    acc[2][j] = fmaf(k2, vv, acc[2][j]);
                    acc[3][j] = fmaf(k3, vv, acc[3][j]);
                }
            }
            #pragma unroll
            for (int i = 0; i < 4; i++)
                #pragma unroll
                for (int j = 0; j < 8; j++)
                    S[(td + i) * PE + te + j] = ex[i] * acc[i][j];
        }
    }
}

// ---------------------------------------------------------------------------
// per-head RMSNorm over dv=256 + swish gate
// ---------------------------------------------------------------------------
__global__ __launch_bounds__(256) void gnorm_gate_kernel(
    const float* __restrict__ o, const float* __restrict__ gout,
    const float* __restrict__ w, float* __restrict__ y)
{
    __shared__ float red8[8];
    size_t idx = (size_t)blockIdx.x * 256 + threadIdx.x;
    float val = o[idx];
    float tot = block_reduce_sum_256(val * val, red8);
    float r = rsqrtf(tot / (float)DV + EPS);
    float gv = gout[idx];
    y[idx] = val * r * w[threadIdx.x] * gv * sigmoidf_(gv);
}

// ---------------------------------------------------------------------------
// Launch
// ---------------------------------------------------------------------------
extern "C" void kernel_launch(void* const* d_in, const int* in_sizes, int n_in,
                              void* d_out, int out_size)
{
    (void)in_sizes; (void)n_in; (void)out_size;
    const float* x         = (const float*)d_in[0];
    const float* attn_w    = (const float*)d_in[1];
    const float* Wq        = (const float*)d_in[2];
    const float* Wk        = (const float*)d_in[3];
    const float* Wv        = (const float*)d_in[4];
    const float* Wg        = (const float*)d_in[5];
    const float* Wgk1      = (const float*)d_in[6];
    const float* Wgk2      = (const float*)d_in[7];
    const float* bgk2      = (const float*)d_in[8];
    const float* gnorm_w   = (const float*)d_in[9];
    const float* Wo        = (const float*)d_in[10];
    const float* mlp_w     = (const float*)d_in[11];
    const float* W_gate    = (const float*)d_in[12];
    const float* W_up      = (const float*)d_in[13];
    const float* W_down    = (const float*)d_in[14];
    float* out             = (float*)d_out;

    float* sc = nullptr;
    cudaGetSymbolAddress((void**)&sc, g_scratch);

    float* h_    = sc + OFF_H;
    float* q_    = sc + OFF_Q;
    float* k_    = sc + OFF_K;
    float* v_    = sc + OFF_V;
    float* gout_ = sc + OFF_GOUT;
    float* glow_ = sc + OFF_GLOW;
    float* glog_ = sc + OFF_GLOG;
    float* gla_  = sc + OFF_GLA;
    float* up_   = sc + OFF_UP;

    float* og_  = v_;      // v dead after gnorm_gate
    float* x2_  = gout_;   // gout dead after gnorm_gate
    float* n_   = h_;      // h dead after projections
    float* tmp_ = gla_;    // gla dead after gnorm_gate

    cudaFuncSetAttribute(gla_attn_kernel,
                         cudaFuncAttributeMaxDynamicSharedMemorySize,
                         GLA_SMEM_BYTES);

    // 1. h = rms(x)
    rmsnorm1024_kernel<<<NTOK, 256>>>(x, attn_w, h_);

    // 2. projections
    sgemm128_kernel<0><<<dim3(DKTOT / 128, NTOK / 128), 256>>>(h_, Wq, q_, nullptr, NTOK, DKTOT, HS);
    sgemm128_kernel<0><<<dim3(DKTOT / 128, NTOK / 128), 256>>>(h_, Wk, k_, nullptr, NTOK, DKTOT, HS);
    sgemm128_kernel<0><<<dim3(DVTOT / 128, NTOK / 128), 256>>>(h_, Wv, v_, nullptr, NTOK, DVTOT, HS);
    sgemm128_kernel<0><<<dim3(DVTOT / 128, NTOK / 128), 256>>>(h_, Wg, gout_, nullptr, NTOK, DVTOT, HS);

    // 3. low-rank gate logits
    glow_kernel<<<(NTOK * RLOW) / 256, 256>>>(h_, Wgk1, glow_);
    glog_kernel<<<(NTOK * DKTOT) / 256, 256>>>(glow_, Wgk2, bgk2, glog_);

    // 4. chunked GLA
    gla_attn_kernel<<<dim3(4, NH, 4), 256, GLA_SMEM_BYTES>>>(q_, k_, v_, glog_, gla_);

    // 5. per-head rmsnorm + swish gate
    gnorm_gate_kernel<<<NTOK * NH, 256>>>(gla_, gout_, gnorm_w, og_);

    // 6. attn out proj fused with residual: x2 = og@Wo + x
    sgemm128_kernel<1><<<dim3(HS / 128, NTOK / 128), 256>>>(og_, Wo, x2_, x, NTOK, HS, DVTOT);

    // 7. mlp norm
    rmsnorm1024_kernel<<<NTOK, 256>>>(x2_, mlp_w, n_);

    // 8. SwiGLU:  up = n@W_up;  up = silu(n@W_gate) * up (in-place epilogue)
    sgemm128_kernel<0><<<dim3(IMLP / 128, NTOK / 128), 256>>>(n_, W_up, up_, nullptr, NTOK, IMLP, HS);
    sgemm128_kernel<2><<<dim3(IMLP / 128, NTOK / 128), 256>>>(n_, W_gate, up_, up_, NTOK, IMLP, HS);

    // 9. down proj fused with residual: out = up@W_down + x2
    sgemm128_kernel<1><<<dim3(HS / 128, NTOK / 128), 256>>>(up_, W_down, out, x2_, NTOK, HS, IMLP);
}

// round 5
// speedup vs baseline: 1.4983x; 1.4983x over previous
#include <cuda_runtime.h>
#include <cuda_bf16.h>
#include <math.h>
#include <stdint.h>

// ---------------------------------------------------------------------------
// Problem constants
// ---------------------------------------------------------------------------
#define NTOK   8192
#define HS     1024
#define DKTOT  512
#define DVTOT  1024
#define NH     4
#define DK     128
#define DV     256
#define CH     64
#define NCHUNK 32
#define RLOW   16
#define IMLP   2816
#define EPS    1e-6f
#define GLN    16.0f

// ---------------------------------------------------------------------------
// fp32 scratch
// ---------------------------------------------------------------------------
#define OFF_H     0ull
#define OFF_Q     (OFF_H    + 8388608ull)
#define OFF_K     (OFF_Q    + 4194304ull)
#define OFF_V     (OFF_K    + 4194304ull)
#define OFF_GOUT  (OFF_V    + 8388608ull)
#define OFF_GLOW  (OFF_GOUT + 8388608ull)
#define OFF_GLOG  (OFF_GLOW + 131072ull)
#define OFF_GLA   (OFF_GLOG + 4194304ull)
#define OFF_UP    (OFF_GLA  + 8388608ull)
#define SCRATCH_FLOATS (OFF_UP + 23068672ull)

__device__ float g_scratch[SCRATCH_FLOATS];

// bf16 transposed+split weights: hi plane then lo plane, [N][K]
#define OW_Q     0ull
#define OW_K     (OW_Q    + 1048576ull)
#define OW_V     (OW_K    + 1048576ull)
#define OW_G     (OW_V    + 2097152ull)
#define OW_O     (OW_G    + 2097152ull)
#define OW_GATE  (OW_O    + 2097152ull)
#define OW_UPW   (OW_GATE + 5767168ull)
#define OW_DOWN  (OW_UPW  + 5767168ull)
#define WBF_ELEMS (OW_DOWN + 5767168ull)

__device__ __align__(16) __nv_bfloat16 g_wbf[WBF_ELEMS];

// bf16 activation planes (hi at 0, lo at +plane)
#define ACT_PLANE 8388608ull                // [8192][1024]
__device__ __align__(16) __nv_bfloat16 g_act[2ull * ACT_PLANE];
#define UPA_PLANE 23068672ull               // [8192][2816]
__device__ __align__(16) __nv_bfloat16 g_upa[2ull * UPA_PLANE];

// ---------------------------------------------------------------------------
// math utils
// ---------------------------------------------------------------------------
__device__ __forceinline__ float sigmoidf_(float x) { return 1.0f / (1.0f + expf(-x)); }
__device__ __forceinline__ float logsigmoidf_(float x) {
    return fminf(x, 0.0f) - log1pf(expf(-fabsf(x)));
}
__device__ __forceinline__ float block_reduce_sum_256(float v, float* red8) {
    #pragma unroll
    for (int o = 16; o > 0; o >>= 1) v += __shfl_xor_sync(0xffffffffu, v, o);
    if ((threadIdx.x & 31) == 0) red8[threadIdx.x >> 5] = v;
    __syncthreads();
    float s;
    if (threadIdx.x < 8) {
        s = red8[threadIdx.x];
        #pragma unroll
        for (int o = 4; o > 0; o >>= 1) s += __shfl_xor_sync(0xffu, s, o);
        if (threadIdx.x == 0) red8[0] = s;
    }
    __syncthreads();
    return red8[0];
}
__device__ __forceinline__ void split_bf16(float v, __nv_bfloat16& h, __nv_bfloat16& l) {
    h = __float2bfloat16(v);
    l = __float2bfloat16(v - __bfloat162float(h));
}

// ---------------------------------------------------------------------------
// sm_100-safe PTX helpers
// ---------------------------------------------------------------------------
__device__ __forceinline__ uint32_t smem_u32(const void* p) {
    uint32_t a;
    asm("{ .reg .u64 t; cvta.to.shared.u64 t, %1; cvt.u32.u64 %0, t; }"
        : "=r"(a) : "l"(p));
    return a;
}
__device__ __forceinline__ void cpasync16(uint32_t s, const void* g) {
    asm volatile("cp.async.cg.shared.global [%0], [%1], 16;" :: "r"(s), "l"(g));
}
#define CP_COMMIT() asm volatile("cp.async.commit_group;" ::: "memory")
#define CP_WAIT2()  asm volatile("cp.async.wait_group 2;" ::: "memory")

#define LDSM4(r0, r1, r2, r3, a) \
    asm volatile("ldmatrix.sync.aligned.m8n8.x4.shared.b16 {%0,%1,%2,%3}, [%4];" \
        : "=r"(r0), "=r"(r1), "=r"(r2), "=r"(r3) : "r"(a))

#define MMA16816(d, a, b) \
    asm volatile("mma.sync.aligned.m16n8k16.row.col.f32.bf16.bf16.f32 " \
        "{%0,%1,%2,%3}, {%4,%5,%6,%7}, {%8,%9}, {%0,%1,%2,%3};" \
        : "+f"((d)[0]), "+f"((d)[1]), "+f"((d)[2]), "+f"((d)[3]) \
        : "r"((a)[0]), "r"((a)[1]), "r"((a)[2]), "r"((a)[3]), \
          "r"((b)[0]), "r"((b)[1]))

// ---------------------------------------------------------------------------
// weight transpose + bf16 hi/lo split: W[K,N] fp32 -> hi/lo [N,K] bf16
// ---------------------------------------------------------------------------
__global__ void wconv_kernel(const float* __restrict__ W,
                             __nv_bfloat16* __restrict__ hi,
                             __nv_bfloat16* __restrict__ lo,
                             int K, int N)
{
    __shared__ float t[32][33];
    int k0 = blockIdx.x * 32, n0 = blockIdx.y * 32;
    int tx = threadIdx.x, ty = threadIdx.y;
    #pragma unroll
    for (int i = 0; i < 4; i++)
        t[ty + i * 8][tx] = W[(size_t)(k0 + ty + i * 8) * N + n0 + tx];
    __syncthreads();
    #pragma unroll
    for (int i = 0; i < 4; i++) {
        float v = t[tx][ty + i * 8];
        __nv_bfloat16 h, l;
        split_bf16(v, h, l);
        size_t o = (size_t)(n0 + ty + i * 8) * K + k0 + tx;
        hi[o] = h;
        lo[o] = l;
    }
}

// ---------------------------------------------------------------------------
// HGEMM via mma.sync bf16 with 3-chain hi/lo split.
// C[M,N] = A[M,K] @ B[N,K]^T, A/B given as bf16 hi/lo planes [*,K].
// 128x128x32 tile, 256 threads (8 warps 4x2), 3-stage cp.async.
// EPI: 0 -> C = acc; 1 -> C = acc + E; 2 -> planes = split(silu(acc)*E)
// ---------------------------------------------------------------------------
#define BKP    40                      // padded row stride (bf16 elems)
#define PLANE_B (128 * BKP * 2)        // 10240 bytes
#define STAGE_B (4 * PLANE_B)          // 40960
#define HG_SMEM (3 * STAGE_B)          // 122880

template <int EPI>
__global__ __launch_bounds__(256, 1) void hgemm_kernel(
    const __nv_bfloat16* __restrict__ Ahi, const __nv_bfloat16* __restrict__ Alo,
    const __nv_bfloat16* __restrict__ Bhi, const __nv_bfloat16* __restrict__ Blo,
    float* __restrict__ C, const float* __restrict__ E,
    __nv_bfloat16* __restrict__ Phi, __nv_bfloat16* __restrict__ Plo,
    int N, int K)
{
    extern __shared__ char sm[];
    const uint32_t smb = smem_u32(sm);
    const int tid  = threadIdx.x;
    const int lane = tid & 31;
    const int wid  = tid >> 5;
    const int wm   = (wid >> 1) * 32;   // warp m offset (0..96)
    const int wn   = (wid & 1) * 64;    // warp n offset (0 or 64)
    const int m0   = blockIdx.y * 128;
    const int n0   = blockIdx.x * 128;

    float acc[2][8][4];
    #pragma unroll
    for (int mt = 0; mt < 2; mt++)
        #pragma unroll
        for (int nt = 0; nt < 8; nt++)
            #pragma unroll
            for (int j = 0; j < 4; j++) acc[mt][nt][j] = 0.0f;

    const int nkb = K / 32;

    auto stage_load = [&](int st) {
        const int buf = st % 3;
        const uint32_t sb = smb + buf * STAGE_B;
        const int k0 = st * 32;
        #pragma unroll
        for (int half = 0; half < 2; half++) {
            int ch = tid + half * 256;            // 0..511
            int row = ch >> 2, c = ch & 3;
            uint32_t so = (uint32_t)(row * 80 + ((c ^ (row & 3)) << 4));
            size_t ga = (size_t)(m0 + row) * K + k0 + c * 8;
            size_t gb = (size_t)(n0 + row) * K + k0 + c * 8;
            cpasync16(sb + 0 * PLANE_B + so, Ahi + ga);
            cpasync16(sb + 1 * PLANE_B + so, Alo + ga);
            cpasync16(sb + 2 * PLANE_B + so, Bhi + gb);
            cpasync16(sb + 3 * PLANE_B + so, Blo + gb);
        }
    };

    stage_load(0); CP_COMMIT();
    stage_load(1); CP_COMMIT();

    for (int s = 0; s < nkb; s++) {
        if (s + 2 < nkb) stage_load(s + 2);
        CP_COMMIT();
        CP_WAIT2();
        __syncthreads();

        const uint32_t sb = smb + (s % 3) * STAGE_B;
        #pragma unroll
        for (int kk = 0; kk < 2; kk++) {
            uint32_t ah[2][4], al[2][4];
            #pragma unroll
            for (int mt = 0; mt < 2; mt++) {
                int row = wm + mt * 16 + (lane & 15);
                int c = kk * 2 + (lane >> 4);
                uint32_t so = (uint32_t)(row * 80 + ((c ^ (row & 3)) << 4));
                LDSM4(ah[mt][0], ah[mt][1], ah[mt][2], ah[mt][3], sb + 0 * PLANE_B + so);
                LDSM4(al[mt][0], al[mt][1], al[mt][2], al[mt][3], sb + 1 * PLANE_B + so);
            }
            uint32_t bh[8][2], bl[8][2];
            #pragma unroll
            for (int nt2 = 0; nt2 < 4; nt2++) {
                int row = wn + nt2 * 16 + (lane & 7) + ((lane >> 4) << 3);
                int c = kk * 2 + ((lane >> 3) & 1);
                uint32_t so = (uint32_t)(row * 80 + ((c ^ (row & 3)) << 4));
                LDSM4(bh[2*nt2][0], bh[2*nt2][1], bh[2*nt2+1][0], bh[2*nt2+1][1],
                      sb + 2 * PLANE_B + so);
                LDSM4(bl[2*nt2][0], bl[2*nt2][1], bl[2*nt2+1][0], bl[2*nt2+1][1],
                      sb + 3 * PLANE_B + so);
            }
            #pragma unroll
            for (int mt = 0; mt < 2; mt++)
                #pragma unroll
                for (int nt = 0; nt < 8; nt++) {
                    MMA16816(acc[mt][nt], ah[mt], bh[nt]);
                    MMA16816(acc[mt][nt], ah[mt], bl[nt]);
                    MMA16816(acc[mt][nt], al[mt], bh[nt]);
                }
        }
        __syncthreads();
    }

    // epilogue
    const int r0 = lane >> 2;
    const int cc = (lane & 3) * 2;
    #pragma unroll
    for (int mt = 0; mt < 2; mt++)
        #pragma unroll
        for (int nt = 0; nt < 8; nt++) {
            int grow = m0 + wm + mt * 16 + r0;
            int gcol = n0 + wn + nt * 8 + cc;
            #pragma unroll
            for (int hrow = 0; hrow < 2; hrow++) {
                size_t off = (size_t)(grow + hrow * 8) * N + gcol;
                float v0 = acc[mt][nt][hrow * 2 + 0];
                float v1 = acc[mt][nt][hrow * 2 + 1];
                if (EPI == 0) {
                    *(float2*)(C + off) = make_float2(v0, v1);
                } else if (EPI == 1) {
                    float2 e = *(const float2*)(E + off);
                    *(float2*)(C + off) = make_float2(v0 + e.x, v1 + e.y);
                } else {  // EPI == 2: silu(acc)*E -> bf16 planes
                    float2 e = *(const float2*)(E + off);
                    v0 = v0 * sigmoidf_(v0) * e.x;
                    v1 = v1 * sigmoidf_(v1) * e.y;
                    __nv_bfloat16 h0, l0, h1, l1;
                    split_bf16(v0, h0, l0);
                    split_bf16(v1, h1, l1);
                    __nv_bfloat162 hp, lp;
                    hp.x = h0; hp.y = h1; lp.x = l0; lp.y = l1;
                    *(__nv_bfloat162*)(Phi + off) = hp;
                    *(__nv_bfloat162*)(Plo + off) = lp;
                }
            }
        }
}

// ---------------------------------------------------------------------------
// RMSNorm over 1024-wide rows; optional fp32 out + bf16 hi/lo planes
// ---------------------------------------------------------------------------
__global__ __launch_bounds__(256) void rmsnorm1024_kernel(
    const float* __restrict__ x, const float* __restrict__ w,
    float* __restrict__ y,
    __nv_bfloat16* __restrict__ phi, __nv_bfloat16* __restrict__ plo)
{
    __shared__ float red8[8];
    const size_t row = blockIdx.x;
    const float4* xr = (const float4*)(x + row * (size_t)HS);
    float4 v = xr[threadIdx.x];
    float ss = v.x * v.x + v.y * v.y + v.z * v.z + v.w * v.w;
    float tot = block_reduce_sum_256(ss, red8);
    float r = rsqrtf(tot / (float)HS + EPS);
    const float4* wr = (const float4*)w;
    float4 wv = wr[threadIdx.x];
    float o[4];
    o[0] = v.x * r * wv.x; o[1] = v.y * r * wv.y;
    o[2] = v.z * r * wv.z; o[3] = v.w * r * wv.w;
    if (y)
        ((float4*)(y + row * (size_t)HS))[threadIdx.x] =
            make_float4(o[0], o[1], o[2], o[3]);
    size_t po = row * (size_t)HS + threadIdx.x * 4;
    __nv_bfloat16 h[4], l[4];
    #pragma unroll
    for (int j = 0; j < 4; j++) split_bf16(o[j], h[j], l[j]);
    __nv_bfloat162 hp0, hp1, lp0, lp1;
    hp0.x = h[0]; hp0.y = h[1]; hp1.x = h[2]; hp1.y = h[3];
    lp0.x = l[0]; lp0.y = l[1]; lp1.x = l[2]; lp1.y = l[3];
    *(__nv_bfloat162*)(phi + po)     = hp0;
    *(__nv_bfloat162*)(phi + po + 2) = hp1;
    *(__nv_bfloat162*)(plo + po)     = lp0;
    *(__nv_bfloat162*)(plo + po + 2) = lp1;
}

// ---------------------------------------------------------------------------
// low-rank gate
// ---------------------------------------------------------------------------
__global__ __launch_bounds__(256) void glow_kernel(
    const float* __restrict__ h, const float* __restrict__ Wgk1,
    float* __restrict__ glow)
{
    int idx = blockIdx.x * 256 + threadIdx.x;
    int m = idx >> 4;
    int r = idx & 15;
    const float* hr = h + (size_t)m * HS;
    float acc = 0.0f;
    #pragma unroll 8
    for (int k = 0; k < HS; k++)
        acc = fmaf(hr[k], Wgk1[(size_t)k * RLOW + r], acc);
    glow[idx] = acc;
}

__global__ __launch_bounds__(256) void glog_kernel(
    const float* __restrict__ glow, const float* __restrict__ Wgk2,
    const float* __restrict__ bgk2, float* __restrict__ glog)
{
    int idx = blockIdx.x * 256 + threadIdx.x;
    int m = idx >> 9;
    int n = idx & 511;
    const float* gr = glow + (size_t)m * RLOW;
    float acc = bgk2[n];
    #pragma unroll
    for (int r = 0; r < RLOW; r++)
        acc = fmaf(gr[r], Wgk2[(size_t)r * DKTOT + n], acc);
    glog[idx] = logsigmoidf_(acc) / GLN;
}

// ---------------------------------------------------------------------------
// GLA chunked attention (unchanged)
// ---------------------------------------------------------------------------
#define DKP 129
#define PE  65
#define GLA_SMEM_FLOATS (128*PE + 3*CH*DKP + 2*CH*PE)
#define GLA_SMEM_BYTES  (GLA_SMEM_FLOATS * 4)

__global__ __launch_bounds__(256) void gla_attn_kernel(
    const float* __restrict__ q, const float* __restrict__ k,
    const float* __restrict__ v, const float* __restrict__ g,
    float* __restrict__ out)
{
    extern __shared__ float gla_sm[];
    const int ev = blockIdx.x;
    const int h  = blockIdx.y;
    const int b  = blockIdx.z;
    const int tid = threadIdx.x;

    float* S   = gla_sm;
    float* qe  = S  + 128 * PE;
    float* kd  = qe + CH * DKP;
    float* bc  = kd + CH * DKP;
    float* vs  = bc + CH * DKP;
    float* Am  = vs + CH * PE;

    for (int i = tid; i < 128 * PE; i += 256) S[i] = 0.0f;

    const float scale = rsqrtf((float)DK);
    const size_t baseqk = ((size_t)b * 2048) * DKTOT + (size_t)h * DK;
    const size_t basev  = ((size_t)b * 2048) * DVTOT + (size_t)h * DV + (size_t)ev * 64;
    const float* qb = q + baseqk;
    const float* kb = k + baseqk;
    const float* gb = g + baseqk;
    const float* vb = v + basev;
    float* ob = out + basev;

    for (int n = 0; n < NCHUNK; n++) {
        const int t0 = n * CH;
        __syncthreads();

        if (tid < DK) {
            float run = 0.0f;
            #pragma unroll 8
            for (int c = 0; c < CH; c++) {
                run += gb[(size_t)(t0 + c) * DKTOT + tid];
                bc[c * DKP + tid] = run;
            }
        }
        for (int i = tid; i < CH * 64; i += 256) {
            int c = i >> 6, e = i & 63;
            vs[c * PE + e] = vb[(size_t)(t0 + c) * DVTOT + e];
        }
        __syncthreads();

        for (int i = tid; i < CH * DK; i += 256) {
            int c = i >> 7, d = i & 127;
            float bv = bc[c * DKP + d];
            size_t gi = (size_t)(t0 + c) * DKTOT + d;
            qe[c * DKP + d] = qb[gi] * expf(bv) * scale;
            kd[c * DKP + d] = kb[gi] * expf(-bv);
        }
        __syncthreads();

        {
            const int tc = (tid >> 4) * 4;
            const int ts = (tid & 15) * 4;
            float acc[4][4];
            #pragma unroll
            for (int i = 0; i < 4; i++)
                #pragma unroll
                for (int j = 0; j < 4; j++) acc[i][j] = 0.0f;
            for (int d = 0; d < DK; d++) {
                float a0 = qe[(tc + 0) * DKP + d];
                float a1 = qe[(tc + 1) * DKP + d];
                float a2 = qe[(tc + 2) * DKP + d];
                float a3 = qe[(tc + 3) * DKP + d];
                float b0 = kd[(ts + 0) * DKP + d];
                float b1 = kd[(ts + 1) * DKP + d];
                float b2 = kd[(ts + 2) * DKP + d];
                float b3 = kd[(ts + 3) * DKP + d];
                acc[0][0] = fmaf(a0, b0, acc[0][0]); acc[0][1] = fmaf(a0, b1, acc[0][1]);
                acc[0][2] = fmaf(a0, b2, acc[0][2]); acc[0][3] = fmaf(a0, b3, acc[0][3]);
                acc[1][0] = fmaf(a1, b0, acc[1][0]); acc[1][1] = fmaf(a1, b1, acc[1][1]);
                acc[1][2] = fmaf(a1, b2, acc[1][2]); acc[1][3] = fmaf(a1, b3, acc[1][3]);
                acc[2][0] = fmaf(a2, b0, acc[2][0]); acc[2][1] = fmaf(a2, b1, acc[2][1]);
                acc[2][2] = fmaf(a2, b2, acc[2][2]); acc[2][3] = fmaf(a2, b3, acc[2][3]);
                acc[3][0] = fmaf(a3, b0, acc[3][0]); acc[3][1] = fmaf(a3, b1, acc[3][1]);
                acc[3][2] = fmaf(a3, b2, acc[3][2]); acc[3][3] = fmaf(a3, b3, acc[3][3]);
            }
            #pragma unroll
            for (int i = 0; i < 4; i++)
                #pragma unroll
                for (int j = 0; j < 4; j++)
                    Am[(tc + i) * PE + ts + j] =
                        (tc + i >= ts + j) ? acc[i][j] : 0.0f;
        }
        __syncthreads();

        {
            const int tc = (tid >> 4) * 4;
            const int te = (tid & 15) * 4;
            float acc[4][4];
            #pragma unroll
            for (int i = 0; i < 4; i++)
                #pragma unroll
                for (int j = 0; j < 4; j++) acc[i][j] = 0.0f;
            for (int s = 0; s < CH; s++) {
                float a0 = Am[(tc + 0) * PE + s];
                float a1 = Am[(tc + 1) * PE + s];
                float a2 = Am[(tc + 2) * PE + s];
                float a3 = Am[(tc + 3) * PE + s];
                float v0 = vs[s * PE + te + 0];
                float v1 = vs[s * PE + te + 1];
                float v2 = vs[s * PE + te + 2];
                float v3 = vs[s * PE + te + 3];
                acc[0][0] = fmaf(a0, v0, acc[0][0]); acc[0][1] = fmaf(a0, v1, acc[0][1]);
                acc[0][2] = fmaf(a0, v2, acc[0][2]); acc[0][3] = fmaf(a0, v3, acc[0][3]);
                acc[1][0] = fmaf(a1, v0, acc[1][0]); acc[1][1] = fmaf(a1, v1, acc[1][1]);
                acc[1][2] = fmaf(a1, v2, acc[1][2]); acc[1][3] = fmaf(a1, v3, acc[1][3]);
                acc[2][0] = fmaf(a2, v0, acc[2][0]); acc[2][1] = fmaf(a2, v1, acc[2][1]);
                acc[2][2] = fmaf(a2, v2, acc[2][2]); acc[2][3] = fmaf(a2, v3, acc[2][3]);
                acc[3][0] = fmaf(a3, v0, acc[3][0]); acc[3][1] = fmaf(a3, v1, acc[3][1]);
                acc[3][2] = fmaf(a3, v2, acc[3][2]); acc[3][3] = fmaf(a3, v3, acc[3][3]);
            }
            for (int d = 0; d < DK; d++) {
                float a0 = qe[(tc + 0) * DKP + d];
                float a1 = qe[(tc + 1) * DKP + d];
                float a2 = qe[(tc + 2) * DKP + d];
                float a3 = qe[(tc + 3) * DKP + d];
                float s0 = S[d * PE + te + 0];
                float s1 = S[d * PE + te + 1];
                float s2 = S[d * PE + te + 2];
                float s3 = S[d * PE + te + 3];
                acc[0][0] = fmaf(a0, s0, acc[0][0]); acc[0][1] = fmaf(a0, s1, acc[0][1]);
                acc[0][2] = fmaf(a0, s2, acc[0][2]); acc[0][3] = fmaf(a0, s3, acc[0][3]);
                acc[1][0] = fmaf(a1, s0, acc[1][0]); acc[1][1] = fmaf(a1, s1, acc[1][1]);
                acc[1][2] = fmaf(a1, s2, acc[1][2]); acc[1][3] = fmaf(a1, s3, acc[1][3]);
                acc[2][0] = fmaf(a2, s0, acc[2][0]); acc[2][1] = fmaf(a2, s1, acc[2][1]);
                acc[2][2] = fmaf(a2, s2, acc[2][2]); acc[2][3] = fmaf(a2, s3, acc[2][3]);
                acc[3][0] = fmaf(a3, s0, acc[3][0]); acc[3][1] = fmaf(a3, s1, acc[3][1]);
                acc[3][2] = fmaf(a3, s2, acc[3][2]); acc[3][3] = fmaf(a3, s3, acc[3][3]);
            }
            #pragma unroll
            for (int i = 0; i < 4; i++)
                #pragma unroll
                for (int j = 0; j < 4; j++)
                    ob[(size_t)(t0 + tc + i) * DVTOT + te + j] = acc[i][j];
        }
        __syncthreads();

        {
            const int td = (tid & 31) * 4;
            const int te = (tid >> 5) * 8;
            float ex[4];
            #pragma unroll
            for (int i = 0; i < 4; i++) ex[i] = expf(bc[63 * DKP + td + i]);
            float acc[4][8];
            #pragma unroll
            for (int i = 0; i < 4; i++)
                #pragma unroll
                for (int j = 0; j < 8; j++)
                    acc[i][j] = S[(td + i) * PE + te + j];
            for (int c = 0; c < CH; c++) {
                float k0 = kd[c * DKP + td + 0];
                float k1 = kd[c * DKP + td + 1];
                float k2 = kd[c * DKP + td + 2];
                float k3 = kd[c * DKP + td + 3];
                #pragma unroll
                for (int j = 0; j < 8; j++) {
                    float vv = vs[c * PE + te + j];
                    acc[0][j] = fmaf(k0, vv, acc[0][j]);
                    acc[1][j] = fmaf(k1, vv, acc[1][j]);
                    acc[2][j] = fmaf(k2, vv, acc[2][j]);
                    acc[3][j] = fmaf(k3, vv, acc[3][j]);
                }
            }
            #pragma unroll
            for (int i = 0; i < 4; i++)
                #pragma unroll
                for (int j = 0; j < 8; j++)
                    S[(td + i) * PE + te + j] = ex[i] * acc[i][j];
        }
    }
}

// ---------------------------------------------------------------------------
// per-head RMSNorm + swish gate -> bf16 planes (no fp32 out needed)
// ---------------------------------------------------------------------------
__global__ __launch_bounds__(256) void gnorm_gate_kernel(
    const float* __restrict__ o, const float* __restrict__ gout,
    const float* __restrict__ w,
    __nv_bfloat16* __restrict__ phi, __nv_bfloat16* __restrict__ plo)
{
    __shared__ float red8[8];
    size_t idx = (size_t)blockIdx.x * 256 + threadIdx.x;
    float val = o[idx];
    float tot = block_reduce_sum_256(val * val, red8);
    float r = rsqrtf(tot / (float)DV + EPS);
    float gv = gout[idx];
    float y = val * r * w[threadIdx.x] * gv * sigmoidf_(gv);
    __nv_bfloat16 h, l;
    split_bf16(y, h, l);
    phi[idx] = h;
    plo[idx] = l;
}

// ---------------------------------------------------------------------------
// Launch
// ---------------------------------------------------------------------------
extern "C" void kernel_launch(void* const* d_in, const int* in_sizes, int n_in,
                              void* d_out, int out_size)
{
    (void)in_sizes; (void)n_in; (void)out_size;
    const float* x         = (const float*)d_in[0];
    const float* attn_w    = (const float*)d_in[1];
    const float* Wq        = (const float*)d_in[2];
    const float* Wk        = (const float*)d_in[3];
    const float* Wv        = (const float*)d_in[4];
    const float* Wg        = (const float*)d_in[5];
    const float* Wgk1      = (const float*)d_in[6];
    const float* Wgk2      = (const float*)d_in[7];
    const float* bgk2      = (const float*)d_in[8];
    const float* gnorm_w   = (const float*)d_in[9];
    const float* Wo        = (const float*)d_in[10];
    const float* mlp_w     = (const float*)d_in[11];
    const float* W_gate    = (const float*)d_in[12];
    const float* W_up      = (const float*)d_in[13];
    const float* W_down    = (const float*)d_in[14];
    float* out             = (float*)d_out;

    float* sc = nullptr;
    cudaGetSymbolAddress((void**)&sc, g_scratch);
    __nv_bfloat16* wb = nullptr;
    cudaGetSymbolAddress((void**)&wb, g_wbf);
    __nv_bfloat16* act = nullptr;
    cudaGetSymbolAddress((void**)&act, g_act);
    __nv_bfloat16* upa = nullptr;
    cudaGetSymbolAddress((void**)&upa, g_upa);

    float* h_    = sc + OFF_H;
    float* q_    = sc + OFF_Q;
    float* k_    = sc + OFF_K;
    float* v_    = sc + OFF_V;
    float* gout_ = sc + OFF_GOUT;
    float* glow_ = sc + OFF_GLOW;
    float* glog_ = sc + OFF_GLOG;
    float* gla_  = sc + OFF_GLA;
    float* up_   = sc + OFF_UP;
    float* x2_   = gout_;     // gout dead after gnorm_gate

    __nv_bfloat16* actHi = act;
    __nv_bfloat16* actLo = act + ACT_PLANE;
    __nv_bfloat16* upHi  = upa;
    __nv_bfloat16* upLo  = upa + UPA_PLANE;

    cudaFuncSetAttribute(gla_attn_kernel,
                         cudaFuncAttributeMaxDynamicSharedMemorySize, GLA_SMEM_BYTES);
    cudaFuncSetAttribute(hgemm_kernel<0>,
                         cudaFuncAttributeMaxDynamicSharedMemorySize, HG_SMEM);
    cudaFuncSetAttribute(hgemm_kernel<1>,
                         cudaFuncAttributeMaxDynamicSharedMemorySize, HG_SMEM);
    cudaFuncSetAttribute(hgemm_kernel<2>,
                         cudaFuncAttributeMaxDynamicSharedMemorySize, HG_SMEM);

    dim3 tb(32, 8);
    wconv_kernel<<<dim3(HS/32,  DKTOT/32), tb>>>(Wq,     wb + OW_Q,    wb + OW_Q    + 524288,  HS,   DKTOT);
    wconv_kernel<<<dim3(HS/32,  DKTOT/32), tb>>>(Wk,     wb + OW_K,    wb + OW_K    + 524288,  HS,   DKTOT);
    wconv_kernel<<<dim3(HS/32,  DVTOT/32), tb>>>(Wv,     wb + OW_V,    wb + OW_V    + 1048576, HS,   DVTOT);
    wconv_kernel<<<dim3(HS/32,  DVTOT/32), tb>>>(Wg,     wb + OW_G,    wb + OW_G    + 1048576, HS,   DVTOT);
    wconv_kernel<<<dim3(DVTOT/32, HS/32),  tb>>>(Wo,     wb + OW_O,    wb + OW_O    + 1048576, DVTOT, HS);
    wconv_kernel<<<dim3(HS/32,  IMLP/32),  tb>>>(W_gate, wb + OW_GATE, wb + OW_GATE + 2883584, HS,   IMLP);
    wconv_kernel<<<dim3(HS/32,  IMLP/32),  tb>>>(W_up,   wb + OW_UPW,  wb + OW_UPW  + 2883584, HS,   IMLP);
    wconv_kernel<<<dim3(IMLP/32, HS/32),   tb>>>(W_down, wb + OW_DOWN, wb + OW_DOWN + 2883584, IMLP, HS);

    // 1. h = rms(x) (fp32 for glow + bf16 planes for GEMMs)
    rmsnorm1024_kernel<<<NTOK, 256>>>(x, attn_w, h_, actHi, actLo);

    // 2. projections via tensor-core HGEMM
    hgemm_kernel<0><<<dim3(DKTOT/128, NTOK/128), 256, HG_SMEM>>>(
        actHi, actLo, wb + OW_Q, wb + OW_Q + 524288, q_, nullptr, nullptr, nullptr, DKTOT, HS);
    hgemm_kernel<0><<<dim3(DKTOT/128, NTOK/128), 256, HG_SMEM>>>(
        actHi, actLo, wb + OW_K, wb + OW_K + 524288, k_, nullptr, nullptr, nullptr, DKTOT, HS);
    hgemm_kernel<0><<<dim3(DVTOT/128, NTOK/128), 256, HG_SMEM>>>(
        actHi, actLo, wb + OW_V, wb + OW_V + 1048576, v_, nullptr, nullptr, nullptr, DVTOT, HS);
    hgemm_kernel<0><<<dim3(DVTOT/128, NTOK/128), 256, HG_SMEM>>>(
        actHi, actLo, wb + OW_G, wb + OW_G + 1048576, gout_, nullptr, nullptr, nullptr, DVTOT, HS);

    // 3. low-rank gate logits
    glow_kernel<<<(NTOK * RLOW) / 256, 256>>>(h_, Wgk1, glow_);
    glog_kernel<<<(NTOK * DKTOT) / 256, 256>>>(glow_, Wgk2, bgk2, glog_);

    // 4. chunked GLA
    gla_attn_kernel<<<dim3(4, NH, 4), 256, GLA_SMEM_BYTES>>>(q_, k_, v_, glog_, gla_);

    // 5. per-head rmsnorm + swish gate -> og planes (reuse act buffer)
    gnorm_gate_kernel<<<NTOK * NH, 256>>>(gla_, gout_, gnorm_w, actHi, actLo);

    // 6. x2 = og@Wo + x
    hgemm_kernel<1><<<dim3(HS/128, NTOK/128), 256, HG_SMEM>>>(
        actHi, actLo, wb + OW_O, wb + OW_O + 1048576, x2_, x, nullptr, nullptr, HS, DVTOT);

    // 7. mlp norm -> n planes (reuse act buffer)
    rmsnorm1024_kernel<<<NTOK, 256>>>(x2_, mlp_w, nullptr, actHi, actLo);

    // 8. SwiGLU: up = n@W_up (fp32); planes = split(silu(n@W_gate) * up)
    hgemm_kernel<0><<<dim3(IMLP/128, NTOK/128), 256, HG_SMEM>>>(
        actHi, actLo, wb + OW_UPW, wb + OW_UPW + 2883584, up_, nullptr, nullptr, nullptr, IMLP, HS);
    hgemm_kernel<2><<<dim3(IMLP/128, NTOK/128), 256, HG_SMEM>>>(
        actHi, actLo, wb + OW_GATE, wb + OW_GATE + 2883584, nullptr, up_, upHi, upLo, IMLP, HS);

    // 9. out = up@W_down + x2
    hgemm_kernel<1><<<dim3(HS/128, NTOK/128), 256, HG_SMEM>>>(
        upHi, upLo, wb + OW_DOWN, wb + OW_DOWN + 2883584, out, x2_, nullptr, nullptr, HS, IMLP);
}

// round 6
// speedup vs baseline: 1.7769x; 1.1859x over previous
#include <cuda_runtime.h>
#include <cuda_bf16.h>
#include <math.h>
#include <stdint.h>

// ---------------------------------------------------------------------------
// Problem constants
// ---------------------------------------------------------------------------
#define NTOK   8192
#define HS     1024
#define DKTOT  512
#define DVTOT  1024
#define NH     4
#define DK     128
#define DV     256
#define CH     64
#define NCHUNK 32
#define RLOW   16
#define IMLP   2816
#define EPS    1e-6f
#define GLN    16.0f
#define QS     3072            // fused QKVG row stride

// ---------------------------------------------------------------------------
// fp32 scratch
// ---------------------------------------------------------------------------
#define OFF_H     0ull                        // 8388608 (8192x1024)
#define OFF_QKVG  (OFF_H    + 8388608ull)     // 25165824 (8192x3072); reused as x2
#define OFF_GLOW  (OFF_QKVG + 25165824ull)    // 131072
#define OFF_GLOG  (OFF_GLOW + 131072ull)      // 4194304
#define OFF_GLA   (OFF_GLOG + 4194304ull)     // 8388608
#define OFF_UP    (OFF_GLA  + 8388608ull)     // 23068672
#define SCRATCH_FLOATS (OFF_UP + 23068672ull)

__device__ float g_scratch[SCRATCH_FLOATS];

// bf16 weights, transposed [N][K], hi plane then lo plane per weight group
#define OW_QKVG  0ull                          // 2 * 3145728  (3072x1024)
#define OW_O     (OW_QKVG + 6291456ull)        // 2 * 1048576
#define OW_GATE  (OW_O    + 2097152ull)        // 2 * 2883584
#define OW_UPW   (OW_GATE + 5767168ull)
#define OW_DOWN  (OW_UPW  + 5767168ull)
#define WBF_ELEMS (OW_DOWN + 5767168ull)

__device__ __align__(16) __nv_bfloat16 g_wbf[WBF_ELEMS];

// bf16 activation planes
#define ACT_PLANE 8388608ull
__device__ __align__(16) __nv_bfloat16 g_act[2ull * ACT_PLANE];
#define UPA_PLANE 23068672ull
__device__ __align__(16) __nv_bfloat16 g_upa[2ull * UPA_PLANE];

// ---------------------------------------------------------------------------
// math utils
// ---------------------------------------------------------------------------
__device__ __forceinline__ float sigmoidf_(float x) { return 1.0f / (1.0f + expf(-x)); }
__device__ __forceinline__ float logsigmoidf_(float x) {
    return fminf(x, 0.0f) - log1pf(expf(-fabsf(x)));
}
__device__ __forceinline__ float block_reduce_sum_256(float v, float* red8) {
    #pragma unroll
    for (int o = 16; o > 0; o >>= 1) v += __shfl_xor_sync(0xffffffffu, v, o);
    if ((threadIdx.x & 31) == 0) red8[threadIdx.x >> 5] = v;
    __syncthreads();
    float s;
    if (threadIdx.x < 8) {
        s = red8[threadIdx.x];
        #pragma unroll
        for (int o = 4; o > 0; o >>= 1) s += __shfl_xor_sync(0xffu, s, o);
        if (threadIdx.x == 0) red8[0] = s;
    }
    __syncthreads();
    return red8[0];
}
__device__ __forceinline__ void split_bf16(float v, __nv_bfloat16& h, __nv_bfloat16& l) {
    h = __float2bfloat16(v);
    l = __float2bfloat16(v - __bfloat162float(h));
}

// ---------------------------------------------------------------------------
// PTX helpers (sm_100-safe)
// ---------------------------------------------------------------------------
__device__ __forceinline__ uint32_t smem_u32(const void* p) {
    uint32_t a;
    asm("{ .reg .u64 t; cvta.to.shared.u64 t, %1; cvt.u32.u64 %0, t; }"
        : "=r"(a) : "l"(p));
    return a;
}
__device__ __forceinline__ void cpasync16(uint32_t s, const void* g) {
    asm volatile("cp.async.cg.shared.global [%0], [%1], 16;" :: "r"(s), "l"(g));
}
#define CP_COMMIT() asm volatile("cp.async.commit_group;" ::: "memory")
#define CP_WAIT1()  asm volatile("cp.async.wait_group 1;" ::: "memory")
#define CP_WAIT0()  asm volatile("cp.async.wait_group 0;" ::: "memory")

#define LDSM4(r0, r1, r2, r3, a) \
    asm volatile("ldmatrix.sync.aligned.m8n8.x4.shared.b16 {%0,%1,%2,%3}, [%4];" \
        : "=r"(r0), "=r"(r1), "=r"(r2), "=r"(r3) : "r"(a))

#define MMA16816(d, a, b) \
    asm volatile("mma.sync.aligned.m16n8k16.row.col.f32.bf16.bf16.f32 " \
        "{%0,%1,%2,%3}, {%4,%5,%6,%7}, {%8,%9}, {%0,%1,%2,%3};" \
        : "+f"((d)[0]), "+f"((d)[1]), "+f"((d)[2]), "+f"((d)[3]) \
        : "r"((a)[0]), "r"((a)[1]), "r"((a)[2]), "r"((a)[3]), \
          "r"((b)[0]), "r"((b)[1]))

// ---------------------------------------------------------------------------
// weight transpose + split
// ---------------------------------------------------------------------------
__global__ void wconv_kernel(const float* __restrict__ W,
                             __nv_bfloat16* __restrict__ hi,
                             __nv_bfloat16* __restrict__ lo,
                             int K, int N)
{
    __shared__ float t[32][33];
    int k0 = blockIdx.x * 32, n0 = blockIdx.y * 32;
    int tx = threadIdx.x, ty = threadIdx.y;
    #pragma unroll
    for (int i = 0; i < 4; i++)
        t[ty + i * 8][tx] = W[(size_t)(k0 + ty + i * 8) * N + n0 + tx];
    __syncthreads();
    #pragma unroll
    for (int i = 0; i < 4; i++) {
        float v = t[tx][ty + i * 8];
        __nv_bfloat16 h, l;
        split_bf16(v, h, l);
        size_t o = (size_t)(n0 + ty + i * 8) * K + k0 + tx;
        hi[o] = h;
        lo[o] = l;
    }
}

// ---------------------------------------------------------------------------
// HGEMM v2: 128x128x32, 2-stage cp.async, 2 CTAs/SM, 3-chain bf16 split.
// EPI: 0 C=acc; 1 C=acc+E; 2 planes=split(silu(acc)*E)
// ---------------------------------------------------------------------------
#define PLANE_B 10240          // 128 rows * 80B
#define STAGE_B (4 * PLANE_B)  // 40960
#define HG_SMEM (2 * STAGE_B)  // 81920

template <int EPI>
__global__ __launch_bounds__(256, 2) void hgemm_kernel(
    const __nv_bfloat16* __restrict__ Ahi, const __nv_bfloat16* __restrict__ Alo,
    const __nv_bfloat16* __restrict__ Bhi, const __nv_bfloat16* __restrict__ Blo,
    float* __restrict__ C, const float* __restrict__ E,
    __nv_bfloat16* __restrict__ Phi, __nv_bfloat16* __restrict__ Plo,
    int N, int K)
{
    extern __shared__ char sm[];
    const uint32_t smb = smem_u32(sm);
    const int tid  = threadIdx.x;
    const int lane = tid & 31;
    const int wid  = tid >> 5;
    const int wm   = (wid >> 1) * 32;
    const int wn   = (wid & 1) * 64;
    const int m0   = blockIdx.y * 128;
    const int n0   = blockIdx.x * 128;

    float acc[2][8][4];
    #pragma unroll
    for (int mt = 0; mt < 2; mt++)
        #pragma unroll
        for (int nt = 0; nt < 8; nt++)
            #pragma unroll
            for (int j = 0; j < 4; j++) acc[mt][nt][j] = 0.0f;

    const int nkb = K / 32;

    auto stage_load = [&](int st) {
        const uint32_t sb = smb + (st & 1) * STAGE_B;
        const int k0 = st * 32;
        #pragma unroll
        for (int half = 0; half < 2; half++) {
            int ch = tid + half * 256;
            int row = ch >> 2, c = ch & 3;
            uint32_t so = (uint32_t)(row * 80 + ((c ^ (row & 3)) << 4));
            size_t ga = (size_t)(m0 + row) * K + k0 + c * 8;
            size_t gb = (size_t)(n0 + row) * K + k0 + c * 8;
            cpasync16(sb + 0 * PLANE_B + so, Ahi + ga);
            cpasync16(sb + 1 * PLANE_B + so, Alo + ga);
            cpasync16(sb + 2 * PLANE_B + so, Bhi + gb);
            cpasync16(sb + 3 * PLANE_B + so, Blo + gb);
        }
    };

    stage_load(0); CP_COMMIT();

    for (int s = 0; s < nkb; s++) {
        if (s + 1 < nkb) { stage_load(s + 1); CP_COMMIT(); CP_WAIT1(); }
        else             { CP_WAIT0(); }
        __syncthreads();

        const uint32_t sb = smb + (s & 1) * STAGE_B;
        #pragma unroll
        for (int kk = 0; kk < 2; kk++) {
            uint32_t ah[2][4], al[2][4];
            #pragma unroll
            for (int mt = 0; mt < 2; mt++) {
                int row = wm + mt * 16 + (lane & 15);
                int c = kk * 2 + (lane >> 4);
                uint32_t so = (uint32_t)(row * 80 + ((c ^ (row & 3)) << 4));
                LDSM4(ah[mt][0], ah[mt][1], ah[mt][2], ah[mt][3], sb + 0 * PLANE_B + so);
                LDSM4(al[mt][0], al[mt][1], al[mt][2], al[mt][3], sb + 1 * PLANE_B + so);
            }
            #pragma unroll
            for (int g = 0; g < 4; g++) {
                uint32_t bh[2][2], bl[2][2];
                int row = wn + g * 16 + (lane & 7) + ((lane >> 4) << 3);
                int c = kk * 2 + ((lane >> 3) & 1);
                uint32_t so = (uint32_t)(row * 80 + ((c ^ (row & 3)) << 4));
                LDSM4(bh[0][0], bh[0][1], bh[1][0], bh[1][1], sb + 2 * PLANE_B + so);
                LDSM4(bl[0][0], bl[0][1], bl[1][0], bl[1][1], sb + 3 * PLANE_B + so);
                #pragma unroll
                for (int mt = 0; mt < 2; mt++)
                    #pragma unroll
                    for (int p = 0; p < 2; p++) {
                        int nt = g * 2 + p;
                        MMA16816(acc[mt][nt], ah[mt], bh[p]);
                        MMA16816(acc[mt][nt], ah[mt], bl[p]);
                        MMA16816(acc[mt][nt], al[mt], bh[p]);
                    }
            }
        }
        __syncthreads();   // compute done before next iter's loads reuse buffer
    }

    // epilogue
    const int r0 = lane >> 2;
    const int cc = (lane & 3) * 2;
    #pragma unroll
    for (int mt = 0; mt < 2; mt++)
        #pragma unroll
        for (int nt = 0; nt < 8; nt++) {
            int grow = m0 + wm + mt * 16 + r0;
            int gcol = n0 + wn + nt * 8 + cc;
            #pragma unroll
            for (int hrow = 0; hrow < 2; hrow++) {
                size_t off = (size_t)(grow + hrow * 8) * N + gcol;
                float v0 = acc[mt][nt][hrow * 2 + 0];
                float v1 = acc[mt][nt][hrow * 2 + 1];
                if (EPI == 0) {
                    *(float2*)(C + off) = make_float2(v0, v1);
                } else if (EPI == 1) {
                    float2 e = *(const float2*)(E + off);
                    *(float2*)(C + off) = make_float2(v0 + e.x, v1 + e.y);
                } else {
                    float2 e = *(const float2*)(E + off);
                    v0 = v0 * sigmoidf_(v0) * e.x;
                    v1 = v1 * sigmoidf_(v1) * e.y;
                    __nv_bfloat16 h0, l0, h1, l1;
                    split_bf16(v0, h0, l0);
                    split_bf16(v1, h1, l1);
                    __nv_bfloat162 hp, lp;
                    hp.x = h0; hp.y = h1; lp.x = l0; lp.y = l1;
                    *(__nv_bfloat162*)(Phi + off) = hp;
                    *(__nv_bfloat162*)(Plo + off) = lp;
                }
            }
        }
}

// ---------------------------------------------------------------------------
// RMSNorm over 1024-wide rows; optional fp32 out + bf16 planes
// ---------------------------------------------------------------------------
__global__ __launch_bounds__(256) void rmsnorm1024_kernel(
    const float* __restrict__ x, const float* __restrict__ w,
    float* __restrict__ y,
    __nv_bfloat16* __restrict__ phi, __nv_bfloat16* __restrict__ plo)
{
    __shared__ float red8[8];
    const size_t row = blockIdx.x;
    const float4* xr = (const float4*)(x + row * (size_t)HS);
    float4 v = xr[threadIdx.x];
    float ss = v.x * v.x + v.y * v.y + v.z * v.z + v.w * v.w;
    float tot = block_reduce_sum_256(ss, red8);
    float r = rsqrtf(tot / (float)HS + EPS);
    const float4* wr = (const float4*)w;
    float4 wv = wr[threadIdx.x];
    float o[4];
    o[0] = v.x * r * wv.x; o[1] = v.y * r * wv.y;
    o[2] = v.z * r * wv.z; o[3] = v.w * r * wv.w;
    if (y)
        ((float4*)(y + row * (size_t)HS))[threadIdx.x] =
            make_float4(o[0], o[1], o[2], o[3]);
    size_t po = row * (size_t)HS + threadIdx.x * 4;
    __nv_bfloat16 h[4], l[4];
    #pragma unroll
    for (int j = 0; j < 4; j++) split_bf16(o[j], h[j], l[j]);
    __nv_bfloat162 hp0, hp1, lp0, lp1;
    hp0.x = h[0]; hp0.y = h[1]; hp1.x = h[2]; hp1.y = h[3];
    lp0.x = l[0]; lp0.y = l[1]; lp1.x = l[2]; lp1.y = l[3];
    *(__nv_bfloat162*)(phi + po)     = hp0;
    *(__nv_bfloat162*)(phi + po + 2) = hp1;
    *(__nv_bfloat162*)(plo + po)     = lp0;
    *(__nv_bfloat162*)(plo + po + 2) = lp1;
}

// ---------------------------------------------------------------------------
// low-rank gate
// ---------------------------------------------------------------------------
__global__ __launch_bounds__(256) void glow_kernel(
    const float* __restrict__ h, const float* __restrict__ Wgk1,
    float* __restrict__ glow)
{
    int idx = blockIdx.x * 256 + threadIdx.x;
    int m = idx >> 4;
    int r = idx & 15;
    const float* hr = h + (size_t)m * HS;
    float acc = 0.0f;
    #pragma unroll 8
    for (int k = 0; k < HS; k++)
        acc = fmaf(hr[k], Wgk1[(size_t)k * RLOW + r], acc);
    glow[idx] = acc;
}

__global__ __launch_bounds__(256) void glog_kernel(
    const float* __restrict__ glow, const float* __restrict__ Wgk2,
    const float* __restrict__ bgk2, float* __restrict__ glog)
{
    int idx = blockIdx.x * 256 + threadIdx.x;
    int m = idx >> 9;
    int n = idx & 511;
    const float* gr = glow + (size_t)m * RLOW;
    float acc = bgk2[n];
    #pragma unroll
    for (int r = 0; r < RLOW; r++)
        acc = fmaf(gr[r], Wgk2[(size_t)r * DKTOT + n], acc);
    glog[idx] = logsigmoidf_(acc) / GLN;
}

// ---------------------------------------------------------------------------
// GLA chunked attention (reads fused QKVG buffer, stride QS)
// ---------------------------------------------------------------------------
#define DKP 129
#define PE  65
#define GLA_SMEM_FLOATS (128*PE + 3*CH*DKP + 2*CH*PE)
#define GLA_SMEM_BYTES  (GLA_SMEM_FLOATS * 4)

__global__ __launch_bounds__(256) void gla_attn_kernel(
    const float* __restrict__ qkvg, const float* __restrict__ g,
    float* __restrict__ out)
{
    extern __shared__ float gla_sm[];
    const int ev = blockIdx.x;
    const int h  = blockIdx.y;
    const int b  = blockIdx.z;
    const int tid = threadIdx.x;

    float* S   = gla_sm;
    float* qe  = S  + 128 * PE;
    float* kd  = qe + CH * DKP;
    float* bc  = kd + CH * DKP;
    float* vs  = bc + CH * DKP;
    float* Am  = vs + CH * PE;

    for (int i = tid; i < 128 * PE; i += 256) S[i] = 0.0f;

    const float scale = rsqrtf((float)DK);
    const size_t rowb = (size_t)b * 2048;
    const float* qb = qkvg + rowb * QS + (size_t)h * DK;          // stride QS
    const float* kb = qb + 512;
    const float* gb = g + rowb * DKTOT + (size_t)h * DK;          // stride 512
    const float* vb = qkvg + rowb * QS + 1024 + (size_t)h * DV + (size_t)ev * 64;
    float* ob = out + rowb * DVTOT + (size_t)h * DV + (size_t)ev * 64;

    for (int n = 0; n < NCHUNK; n++) {
        const int t0 = n * CH;
        __syncthreads();

        if (tid < DK) {
            float run = 0.0f;
            #pragma unroll 8
            for (int c = 0; c < CH; c++) {
                run += gb[(size_t)(t0 + c) * DKTOT + tid];
                bc[c * DKP + tid] = run;
            }
        }
        for (int i = tid; i < CH * 64; i += 256) {
            int c = i >> 6, e = i & 63;
            vs[c * PE + e] = vb[(size_t)(t0 + c) * QS + e];
        }
        __syncthreads();

        for (int i = tid; i < CH * DK; i += 256) {
            int c = i >> 7, d = i & 127;
            float bv = bc[c * DKP + d];
            size_t gi = (size_t)(t0 + c) * QS + d;
            qe[c * DKP + d] = qb[gi] * expf(bv) * scale;
            kd[c * DKP + d] = kb[gi] * expf(-bv);
        }
        __syncthreads();

        {
            const int tc = (tid >> 4) * 4;
            const int ts = (tid & 15) * 4;
            float acc[4][4];
            #pragma unroll
            for (int i = 0; i < 4; i++)
                #pragma unroll
                for (int j = 0; j < 4; j++) acc[i][j] = 0.0f;
            for (int d = 0; d < DK; d++) {
                float a0 = qe[(tc + 0) * DKP + d];
                float a1 = qe[(tc + 1) * DKP + d];
                float a2 = qe[(tc + 2) * DKP + d];
                float a3 = qe[(tc + 3) * DKP + d];
                float b0 = kd[(ts + 0) * DKP + d];
                float b1 = kd[(ts + 1) * DKP + d];
                float b2 = kd[(ts + 2) * DKP + d];
                float b3 = kd[(ts + 3) * DKP + d];
                acc[0][0] = fmaf(a0, b0, acc[0][0]); acc[0][1] = fmaf(a0, b1, acc[0][1]);
                acc[0][2] = fmaf(a0, b2, acc[0][2]); acc[0][3] = fmaf(a0, b3, acc[0][3]);
                acc[1][0] = fmaf(a1, b0, acc[1][0]); acc[1][1] = fmaf(a1, b1, acc[1][1]);
                acc[1][2] = fmaf(a1, b2, acc[1][2]); acc[1][3] = fmaf(a1, b3, acc[1][3]);
                acc[2][0] = fmaf(a2, b0, acc[2][0]); acc[2][1] = fmaf(a2, b1, acc[2][1]);
                acc[2][2] = fmaf(a2, b2, acc[2][2]); acc[2][3] = fmaf(a2, b3, acc[2][3]);
                acc[3][0] = fmaf(a3, b0, acc[3][0]); acc[3][1] = fmaf(a3, b1, acc[3][1]);
                acc[3][2] = fmaf(a3, b2, acc[3][2]); acc[3][3] = fmaf(a3, b3, acc[3][3]);
            }
            #pragma unroll
            for (int i = 0; i < 4; i++)
                #pragma unroll
                for (int j = 0; j < 4; j++)
                    Am[(tc + i) * PE + ts + j] =
                        (tc + i >= ts + j) ? acc[i][j] : 0.0f;
        }
        __syncthreads();

        {
            const int tc = (tid >> 4) * 4;
            const int te = (tid & 15) * 4;
            float acc[4][4];
            #pragma unroll
            for (int i = 0; i < 4; i++)
                #pragma unroll
                for (int j = 0; j < 4; j++) acc[i][j] = 0.0f;
            for (int s = 0; s < CH; s++) {
                float a0 = Am[(tc + 0) * PE + s];
                float a1 = Am[(tc + 1) * PE + s];
                float a2 = Am[(tc + 2) * PE + s];
                float a3 = Am[(tc + 3) * PE + s];
                float v0 = vs[s * PE + te + 0];
                float v1 = vs[s * PE + te + 1];
                float v2 = vs[s * PE + te + 2];
                float v3 = vs[s * PE + te + 3];
                acc[0][0] = fmaf(a0, v0, acc[0][0]); acc[0][1] = fmaf(a0, v1, acc[0][1]);
                acc[0][2] = fmaf(a0, v2, acc[0][2]); acc[0][3] = fmaf(a0, v3, acc[0][3]);
                acc[1][0] = fmaf(a1, v0, acc[1][0]); acc[1][1] = fmaf(a1, v1, acc[1][1]);
                acc[1][2] = fmaf(a1, v2, acc[1][2]); acc[1][3] = fmaf(a1, v3, acc[1][3]);
                acc[2][0] = fmaf(a2, v0, acc[2][0]); acc[2][1] = fmaf(a2, v1, acc[2][1]);
                acc[2][2] = fmaf(a2, v2, acc[2][2]); acc[2][3] = fmaf(a2, v3, acc[2][3]);
                acc[3][0] = fmaf(a3, v0, acc[3][0]); acc[3][1] = fmaf(a3, v1, acc[3][1]);
                acc[3][2] = fmaf(a3, v2, acc[3][2]); acc[3][3] = fmaf(a3, v3, acc[3][3]);
            }
            for (int d = 0; d < DK; d++) {
                float a0 = qe[(tc + 0) * DKP + d];
                float a1 = qe[(tc + 1) * DKP + d];
                float a2 = qe[(tc + 2) * DKP + d];
                float a3 = qe[(tc + 3) * DKP + d];
                float s0 = S[d * PE + te + 0];
                float s1 = S[d * PE + te + 1];
                float s2 = S[d * PE + te + 2];
                float s3 = S[d * PE + te + 3];
                acc[0][0] = fmaf(a0, s0, acc[0][0]); acc[0][1] = fmaf(a0, s1, acc[0][1]);
                acc[0][2] = fmaf(a0, s2, acc[0][2]); acc[0][3] = fmaf(a0, s3, acc[0][3]);
                acc[1][0] = fmaf(a1, s0, acc[1][0]); acc[1][1] = fmaf(a1, s1, acc[1][1]);
                acc[1][2] = fmaf(a1, s2, acc[1][2]); acc[1][3] = fmaf(a1, s3, acc[1][3]);
                acc[2][0] = fmaf(a2, s0, acc[2][0]); acc[2][1] = fmaf(a2, s1, acc[2][1]);
                acc[2][2] = fmaf(a2, s2, acc[2][2]); acc[2][3] = fmaf(a2, s3, acc[2][3]);
                acc[3][0] = fmaf(a3, s0, acc[3][0]); acc[3][1] = fmaf(a3, s1, acc[3][1]);
                acc[3][2] = fmaf(a3, s2, acc[3][2]); acc[3][3] = fmaf(a3, s3, acc[3][3]);
            }
            #pragma unroll
            for (int i = 0; i < 4; i++)
                #pragma unroll
                for (int j = 0; j < 4; j++)
                    ob[(size_t)(t0 + tc + i) * DVTOT + te + j] = acc[i][j];
        }
        __syncthreads();

        {
            const int td = (tid & 31) * 4;
            const int te = (tid >> 5) * 8;
            float ex[4];
            #pragma unroll
            for (int i = 0; i < 4; i++) ex[i] = expf(bc[63 * DKP + td + i]);
            float acc[4][8];
            #pragma unroll
            for (int i = 0; i < 4; i++)
                #pragma unroll
                for (int j = 0; j < 8; j++)
                    acc[i][j] = S[(td + i) * PE + te + j];
            for (int c = 0; c < CH; c++) {
                float k0 = kd[c * DKP + td + 0];
                float k1 = kd[c * DKP + td + 1];
                float k2 = kd[c * DKP + td + 2];
                float k3 = kd[c * DKP + td + 3];
                #pragma unroll
                for (int j = 0; j < 8; j++) {
                    float vv = vs[c * PE + te + j];
                    acc[0][j] = fmaf(k0, vv, acc[0][j]);
                    acc[1][j] = fmaf(k1, vv, acc[1][j]);
                    acc[2][j] = fmaf(k2, vv, acc[2][j]);
                    acc[3][j] = fmaf(k3, vv, acc[3][j]);
                }
            }
            #pragma unroll
            for (int i = 0; i < 4; i++)
                #pragma unroll
                for (int j = 0; j < 8; j++)
                    S[(td + i) * PE + te + j] = ex[i] * acc[i][j];
        }
    }
}

// ---------------------------------------------------------------------------
// per-head RMSNorm + swish gate (gate read from fused QKVG) -> bf16 planes
// ---------------------------------------------------------------------------
__global__ __launch_bounds__(256) void gnorm_gate_kernel(
    const float* __restrict__ o, const float* __restrict__ qkvg,
    const float* __restrict__ w,
    __nv_bfloat16* __restrict__ phi, __nv_bfloat16* __restrict__ plo)
{
    __shared__ float red8[8];
    size_t idx = (size_t)blockIdx.x * 256 + threadIdx.x;
    int token = blockIdx.x >> 2;
    int h = blockIdx.x & 3;
    float val = o[idx];
    float tot = block_reduce_sum_256(val * val, red8);
    float r = rsqrtf(tot / (float)DV + EPS);
    float gv = qkvg[(size_t)token * QS + 2048 + h * 256 + threadIdx.x];
    float y = val * r * w[threadIdx.x] * gv * sigmoidf_(gv);
    __nv_bfloat16 hh, ll;
    split_bf16(y, hh, ll);
    phi[idx] = hh;
    plo[idx] = ll;
}

// ---------------------------------------------------------------------------
// Launch
// ---------------------------------------------------------------------------
extern "C" void kernel_launch(void* const* d_in, const int* in_sizes, int n_in,
                              void* d_out, int out_size)
{
    (void)in_sizes; (void)n_in; (void)out_size;
    const float* x         = (const float*)d_in[0];
    const float* attn_w    = (const float*)d_in[1];
    const float* Wq        = (const float*)d_in[2];
    const float* Wk        = (const float*)d_in[3];
    const float* Wv        = (const float*)d_in[4];
    const float* Wg        = (const float*)d_in[5];
    const float* Wgk1      = (const float*)d_in[6];
    const float* Wgk2      = (const float*)d_in[7];
    const float* bgk2      = (const float*)d_in[8];
    const float* gnorm_w   = (const float*)d_in[9];
    const float* Wo        = (const float*)d_in[10];
    const float* mlp_w     = (const float*)d_in[11];
    const float* W_gate    = (const float*)d_in[12];
    const float* W_up      = (const float*)d_in[13];
    const float* W_down    = (const float*)d_in[14];
    float* out             = (float*)d_out;

    float* sc = nullptr;
    cudaGetSymbolAddress((void**)&sc, g_scratch);
    __nv_bfloat16* wb = nullptr;
    cudaGetSymbolAddress((void**)&wb, g_wbf);
    __nv_bfloat16* act = nullptr;
    cudaGetSymbolAddress((void**)&act, g_act);
    __nv_bfloat16* upa = nullptr;
    cudaGetSymbolAddress((void**)&upa, g_upa);

    float* h_    = sc + OFF_H;
    float* qkvg_ = sc + OFF_QKVG;
    float* glow_ = sc + OFF_GLOW;
    float* glog_ = sc + OFF_GLOG;
    float* gla_  = sc + OFF_GLA;
    float* up_   = sc + OFF_UP;
    float* x2_   = qkvg_;           // qkvg dead after gnorm_gate

    __nv_bfloat16* actHi = act;
    __nv_bfloat16* actLo = act + ACT_PLANE;
    __nv_bfloat16* upHi  = upa;
    __nv_bfloat16* upLo  = upa + UPA_PLANE;

    // fused QKVG weight planes
    __nv_bfloat16* wQKVGhi = wb + OW_QKVG;
    __nv_bfloat16* wQKVGlo = wQKVGhi + 3145728ull;

    cudaFuncSetAttribute(gla_attn_kernel,
                         cudaFuncAttributeMaxDynamicSharedMemorySize, GLA_SMEM_BYTES);
    cudaFuncSetAttribute(hgemm_kernel<0>,
                         cudaFuncAttributeMaxDynamicSharedMemorySize, HG_SMEM);
    cudaFuncSetAttribute(hgemm_kernel<1>,
                         cudaFuncAttributeMaxDynamicSharedMemorySize, HG_SMEM);
    cudaFuncSetAttribute(hgemm_kernel<2>,
                         cudaFuncAttributeMaxDynamicSharedMemorySize, HG_SMEM);

    dim3 tb(32, 8);
    // QKVG concat rows: Q[0:512) K[512:1024) V[1024:2048) G[2048:3072)
    wconv_kernel<<<dim3(HS/32, DKTOT/32), tb>>>(Wq, wQKVGhi,                wQKVGlo,                HS, DKTOT);
    wconv_kernel<<<dim3(HS/32, DKTOT/32), tb>>>(Wk, wQKVGhi +  512ull*HS,   wQKVGlo +  512ull*HS,   HS, DKTOT);
    wconv_kernel<<<dim3(HS/32, DVTOT/32), tb>>>(Wv, wQKVGhi + 1024ull*HS,   wQKVGlo + 1024ull*HS,   HS, DVTOT);
    wconv_kernel<<<dim3(HS/32, DVTOT/32), tb>>>(Wg, wQKVGhi + 2048ull*HS,   wQKVGlo + 2048ull*HS,   HS, DVTOT);
    wconv_kernel<<<dim3(DVTOT/32, HS/32), tb>>>(Wo,     wb + OW_O,    wb + OW_O    + 1048576, DVTOT, HS);
    wconv_kernel<<<dim3(HS/32, IMLP/32),  tb>>>(W_gate, wb + OW_GATE, wb + OW_GATE + 2883584, HS,   IMLP);
    wconv_kernel<<<dim3(HS/32, IMLP/32),  tb>>>(W_up,   wb + OW_UPW,  wb + OW_UPW  + 2883584, HS,   IMLP);
    wconv_kernel<<<dim3(IMLP/32, HS/32),  tb>>>(W_down, wb + OW_DOWN, wb + OW_DOWN + 2883584, IMLP, HS);

    // 1. h = rms(x)
    rmsnorm1024_kernel<<<NTOK, 256>>>(x, attn_w, h_, actHi, actLo);

    // 2. fused QKVG projection (N=3072)
    hgemm_kernel<0><<<dim3(QS/128, NTOK/128), 256, HG_SMEM>>>(
        actHi, actLo, wQKVGhi, wQKVGlo, qkvg_, nullptr, nullptr, nullptr, QS, HS);

    // 3. low-rank gate logits
    glow_kernel<<<(NTOK * RLOW) / 256, 256>>>(h_, Wgk1, glow_);
    glog_kernel<<<(NTOK * DKTOT) / 256, 256>>>(glow_, Wgk2, bgk2, glog_);

    // 4. chunked GLA
    gla_attn_kernel<<<dim3(4, NH, 4), 256, GLA_SMEM_BYTES>>>(qkvg_, glog_, gla_);

    // 5. per-head rmsnorm + swish gate -> og planes
    gnorm_gate_kernel<<<NTOK * NH, 256>>>(gla_, qkvg_, gnorm_w, actHi, actLo);

    // 6. x2 = og@Wo + x   (x2 aliases qkvg, fully consumed above)
    hgemm_kernel<1><<<dim3(HS/128, NTOK/128), 256, HG_SMEM>>>(
        actHi, actLo, wb + OW_O, wb + OW_O + 1048576, x2_, x, nullptr, nullptr, HS, DVTOT);

    // 7. mlp norm -> n planes
    rmsnorm1024_kernel<<<NTOK, 256>>>(x2_, mlp_w, nullptr, actHi, actLo);

    // 8. SwiGLU
    hgemm_kernel<0><<<dim3(IMLP/128, NTOK/128), 256, HG_SMEM>>>(
        actHi, actLo, wb + OW_UPW, wb + OW_UPW + 2883584, up_, nullptr, nullptr, nullptr, IMLP, HS);
    hgemm_kernel<2><<<dim3(IMLP/128, NTOK/128), 256, HG_SMEM>>>(
        actHi, actLo, wb + OW_GATE, wb + OW_GATE + 2883584, nullptr, up_, upHi, upLo, IMLP, HS);

    // 9. out = up@W_down + x2
    hgemm_kernel<1><<<dim3(HS/128, NTOK/128), 256, HG_SMEM>>>(
        upHi, upLo, wb + OW_DOWN, wb + OW_DOWN + 2883584, out, x2_, nullptr, nullptr, HS, IMLP);
}

// round 7
// speedup vs baseline: 2.3637x; 1.3303x over previous
#include <cuda_runtime.h>
#include <cuda_bf16.h>
#include <math.h>
#include <stdint.h>

// ---------------------------------------------------------------------------
// Problem constants
// ---------------------------------------------------------------------------
#define NTOK   8192
#define HS     1024
#define DKTOT  512
#define DVTOT  1024
#define NH     4
#define DK     128
#define DV     256
#define CH     64
#define NCHUNK 32
#define RLOW   16
#define IMLP   2816
#define EPS    1e-6f
#define GLN    16.0f
#define QS     3072            // fused QKVG row stride

// ---------------------------------------------------------------------------
// fp32 scratch
// ---------------------------------------------------------------------------
#define OFF_H     0ull                        // 8388608 (8192x1024)
#define OFF_QKVG  (OFF_H    + 8388608ull)     // 25165824 (8192x3072); reused as x2
#define OFF_GLOW  (OFF_QKVG + 25165824ull)    // 131072
#define OFF_GLOG  (OFF_GLOW + 131072ull)      // 4194304
#define OFF_GLA   (OFF_GLOG + 4194304ull)     // 8388608
#define OFF_UP    (OFF_GLA  + 8388608ull)     // 23068672
#define SCRATCH_FLOATS (OFF_UP + 23068672ull)

__device__ float g_scratch[SCRATCH_FLOATS];

// bf16 weights, transposed [N][K], hi plane then lo plane per weight group
#define OW_QKVG  0ull                          // 2 * 3145728  (3072x1024)
#define OW_O     (OW_QKVG + 6291456ull)        // 2 * 1048576
#define OW_GATE  (OW_O    + 2097152ull)        // 2 * 2883584
#define OW_UPW   (OW_GATE + 5767168ull)
#define OW_DOWN  (OW_UPW  + 5767168ull)
#define WBF_ELEMS (OW_DOWN + 5767168ull)

__device__ __align__(16) __nv_bfloat16 g_wbf[WBF_ELEMS];

// bf16 activation planes
#define ACT_PLANE 8388608ull
__device__ __align__(16) __nv_bfloat16 g_act[2ull * ACT_PLANE];
#define UPA_PLANE 23068672ull
__device__ __align__(16) __nv_bfloat16 g_upa[2ull * UPA_PLANE];

// ---------------------------------------------------------------------------
// math utils
// ---------------------------------------------------------------------------
__device__ __forceinline__ float sigmoidf_(float x) { return 1.0f / (1.0f + expf(-x)); }
__device__ __forceinline__ float logsigmoidf_(float x) {
    return fminf(x, 0.0f) - log1pf(expf(-fabsf(x)));
}
__device__ __forceinline__ float block_reduce_sum_256(float v, float* red8) {
    #pragma unroll
    for (int o = 16; o > 0; o >>= 1) v += __shfl_xor_sync(0xffffffffu, v, o);
    if ((threadIdx.x & 31) == 0) red8[threadIdx.x >> 5] = v;
    __syncthreads();
    float s;
    if (threadIdx.x < 8) {
        s = red8[threadIdx.x];
        #pragma unroll
        for (int o = 4; o > 0; o >>= 1) s += __shfl_xor_sync(0xffu, s, o);
        if (threadIdx.x == 0) red8[0] = s;
    }
    __syncthreads();
    return red8[0];
}
__device__ __forceinline__ void split_bf16(float v, __nv_bfloat16& h, __nv_bfloat16& l) {
    h = __float2bfloat16(v);
    l = __float2bfloat16(v - __bfloat162float(h));
}

// ---------------------------------------------------------------------------
// PTX helpers (sm_100-safe)
// ---------------------------------------------------------------------------
__device__ __forceinline__ uint32_t smem_u32(const void* p) {
    uint32_t a;
    asm("{ .reg .u64 t; cvta.to.shared.u64 t, %1; cvt.u32.u64 %0, t; }"
        : "=r"(a) : "l"(p));
    return a;
}
__device__ __forceinline__ void cpasync16(uint32_t s, const void* g) {
    asm volatile("cp.async.cg.shared.global [%0], [%1], 16;" :: "r"(s), "l"(g));
}
#define CP_COMMIT() asm volatile("cp.async.commit_group;" ::: "memory")
#define CP_WAIT1()  asm volatile("cp.async.wait_group 1;" ::: "memory")
#define CP_WAIT0()  asm volatile("cp.async.wait_group 0;" ::: "memory")

#define LDSM4(r0, r1, r2, r3, a) \
    asm volatile("ldmatrix.sync.aligned.m8n8.x4.shared.b16 {%0,%1,%2,%3}, [%4];" \
        : "=r"(r0), "=r"(r1), "=r"(r2), "=r"(r3) : "r"(a))

#define MMA16816(d, a, b) \
    asm volatile("mma.sync.aligned.m16n8k16.row.col.f32.bf16.bf16.f32 " \
        "{%0,%1,%2,%3}, {%4,%5,%6,%7}, {%8,%9}, {%0,%1,%2,%3};" \
        : "+f"((d)[0]), "+f"((d)[1]), "+f"((d)[2]), "+f"((d)[3]) \
        : "r"((a)[0]), "r"((a)[1]), "r"((a)[2]), "r"((a)[3]), \
          "r"((b)[0]), "r"((b)[1]))

// ---------------------------------------------------------------------------
// weight transpose + split
// ---------------------------------------------------------------------------
__global__ void wconv_kernel(const float* __restrict__ W,
                             __nv_bfloat16* __restrict__ hi,
                             __nv_bfloat16* __restrict__ lo,
                             int K, int N)
{
    __shared__ float t[32][33];
    int k0 = blockIdx.x * 32, n0 = blockIdx.y * 32;
    int tx = threadIdx.x, ty = threadIdx.y;
    #pragma unroll
    for (int i = 0; i < 4; i++)
        t[ty + i * 8][tx] = W[(size_t)(k0 + ty + i * 8) * N + n0 + tx];
    __syncthreads();
    #pragma unroll
    for (int i = 0; i < 4; i++) {
        float v = t[tx][ty + i * 8];
        __nv_bfloat16 h, l;
        split_bf16(v, h, l);
        size_t o = (size_t)(n0 + ty + i * 8) * K + k0 + tx;
        hi[o] = h;
        lo[o] = l;
    }
}

// ---------------------------------------------------------------------------
// HGEMM v3: 128x128x32, 3-stage cp.async, 1 sync/iter, compact XOR swizzle,
// 2 CTAs/SM, 3-chain bf16 split.
// SMEM layout: plane = 128 rows x 64B (32 bf16), chunk swizzle c^((row>>1)&3).
// EPI: 0 C=acc; 1 C=acc+E; 2 planes=split(silu(acc)*E)
// ---------------------------------------------------------------------------
#define SO(row, c) ((uint32_t)(((row) << 6) + ((((c) ^ (((row) >> 1) & 3))) << 4)))
#define PLANE_B 8192           // 128 * 64
#define STAGE_B (4 * PLANE_B)  // 32768
#define HG_SMEM (3 * STAGE_B)  // 98304

template <int EPI>
__global__ __launch_bounds__(256, 2) void hgemm_kernel(
    const __nv_bfloat16* __restrict__ Ahi, const __nv_bfloat16* __restrict__ Alo,
    const __nv_bfloat16* __restrict__ Bhi, const __nv_bfloat16* __restrict__ Blo,
    float* __restrict__ C, const float* __restrict__ E,
    __nv_bfloat16* __restrict__ Phi, __nv_bfloat16* __restrict__ Plo,
    int N, int K)
{
    extern __shared__ char sm[];
    const uint32_t smb = smem_u32(sm);
    const int tid  = threadIdx.x;
    const int lane = tid & 31;
    const int wid  = tid >> 5;
    const int wm   = (wid >> 1) * 32;
    const int wn   = (wid & 1) * 64;
    const int m0   = blockIdx.y * 128;
    const int n0   = blockIdx.x * 128;

    float acc[2][8][4];
    #pragma unroll
    for (int mt = 0; mt < 2; mt++)
        #pragma unroll
        for (int nt = 0; nt < 8; nt++)
            #pragma unroll
            for (int j = 0; j < 4; j++) acc[mt][nt][j] = 0.0f;

    const int nkb = K / 32;

    auto stage_load = [&](int st) {
        const uint32_t sb = smb + (st % 3) * STAGE_B;
        const int k0 = st * 32;
        #pragma unroll
        for (int half = 0; half < 2; half++) {
            int ch = tid + half * 256;          // 0..511
            int row = ch >> 2, c = ch & 3;
            uint32_t so = SO(row, c);
            size_t ga = (size_t)(m0 + row) * K + k0 + c * 8;
            size_t gb = (size_t)(n0 + row) * K + k0 + c * 8;
            cpasync16(sb + 0 * PLANE_B + so, Ahi + ga);
            cpasync16(sb + 1 * PLANE_B + so, Alo + ga);
            cpasync16(sb + 2 * PLANE_B + so, Bhi + gb);
            cpasync16(sb + 3 * PLANE_B + so, Blo + gb);
        }
    };

    stage_load(0); CP_COMMIT();
    stage_load(1); CP_COMMIT();

    for (int s = 0; s < nkb; s++) {
        // wait for own group-s copies, then barrier: publishes everyone's
        // group-s data AND fences compute(s-1) before buffer (s-1)%3 reuse.
        if (s + 1 < nkb) CP_WAIT1(); else CP_WAIT0();
        __syncthreads();
        if (s + 2 < nkb) { stage_load(s + 2); CP_COMMIT(); }

        const uint32_t sb = smb + (s % 3) * STAGE_B;
        #pragma unroll
        for (int kk = 0; kk < 2; kk++) {
            uint32_t ah[2][4], al[2][4];
            #pragma unroll
            for (int mt = 0; mt < 2; mt++) {
                int row = wm + mt * 16 + (lane & 15);
                int c = kk * 2 + (lane >> 4);
                uint32_t so = SO(row, c);
                LDSM4(ah[mt][0], ah[mt][1], ah[mt][2], ah[mt][3], sb + 0 * PLANE_B + so);
                LDSM4(al[mt][0], al[mt][1], al[mt][2], al[mt][3], sb + 1 * PLANE_B + so);
            }
            #pragma unroll
            for (int g = 0; g < 4; g++) {
                uint32_t bh[2][2], bl[2][2];
                int row = wn + g * 16 + (lane & 7) + ((lane >> 4) << 3);
                int c = kk * 2 + ((lane >> 3) & 1);
                uint32_t so = SO(row, c);
                LDSM4(bh[0][0], bh[0][1], bh[1][0], bh[1][1], sb + 2 * PLANE_B + so);
                LDSM4(bl[0][0], bl[0][1], bl[1][0], bl[1][1], sb + 3 * PLANE_B + so);
                #pragma unroll
                for (int mt = 0; mt < 2; mt++)
                    #pragma unroll
                    for (int p = 0; p < 2; p++) {
                        int nt = g * 2 + p;
                        MMA16816(acc[mt][nt], ah[mt], bh[p]);
                        MMA16816(acc[mt][nt], ah[mt], bl[p]);
                        MMA16816(acc[mt][nt], al[mt], bh[p]);
                    }
            }
        }
    }

    // epilogue
    const int r0 = lane >> 2;
    const int cc = (lane & 3) * 2;
    #pragma unroll
    for (int mt = 0; mt < 2; mt++)
        #pragma unroll
        for (int nt = 0; nt < 8; nt++) {
            int grow = m0 + wm + mt * 16 + r0;
            int gcol = n0 + wn + nt * 8 + cc;
            #pragma unroll
            for (int hrow = 0; hrow < 2; hrow++) {
                size_t off = (size_t)(grow + hrow * 8) * N + gcol;
                float v0 = acc[mt][nt][hrow * 2 + 0];
                float v1 = acc[mt][nt][hrow * 2 + 1];
                if (EPI == 0) {
                    *(float2*)(C + off) = make_float2(v0, v1);
                } else if (EPI == 1) {
                    float2 e = *(const float2*)(E + off);
                    *(float2*)(C + off) = make_float2(v0 + e.x, v1 + e.y);
                } else {
                    float2 e = *(const float2*)(E + off);
                    v0 = v0 * sigmoidf_(v0) * e.x;
                    v1 = v1 * sigmoidf_(v1) * e.y;
                    __nv_bfloat16 h0, l0, h1, l1;
                    split_bf16(v0, h0, l0);
                    split_bf16(v1, h1, l1);
                    __nv_bfloat162 hp, lp;
                    hp.x = h0; hp.y = h1; lp.x = l0; lp.y = l1;
                    *(__nv_bfloat162*)(Phi + off) = hp;
                    *(__nv_bfloat162*)(Plo + off) = lp;
                }
            }
        }
}

// ---------------------------------------------------------------------------
// RMSNorm over 1024-wide rows; optional fp32 out + bf16 planes
// ---------------------------------------------------------------------------
__global__ __launch_bounds__(256) void rmsnorm1024_kernel(
    const float* __restrict__ x, const float* __restrict__ w,
    float* __restrict__ y,
    __nv_bfloat16* __restrict__ phi, __nv_bfloat16* __restrict__ plo)
{
    __shared__ float red8[8];
    const size_t row = blockIdx.x;
    const float4* xr = (const float4*)(x + row * (size_t)HS);
    float4 v = xr[threadIdx.x];
    float ss = v.x * v.x + v.y * v.y + v.z * v.z + v.w * v.w;
    float tot = block_reduce_sum_256(ss, red8);
    float r = rsqrtf(tot / (float)HS + EPS);
    const float4* wr = (const float4*)w;
    float4 wv = wr[threadIdx.x];
    float o[4];
    o[0] = v.x * r * wv.x; o[1] = v.y * r * wv.y;
    o[2] = v.z * r * wv.z; o[3] = v.w * r * wv.w;
    if (y)
        ((float4*)(y + row * (size_t)HS))[threadIdx.x] =
            make_float4(o[0], o[1], o[2], o[3]);
    size_t po = row * (size_t)HS + threadIdx.x * 4;
    __nv_bfloat16 h[4], l[4];
    #pragma unroll
    for (int j = 0; j < 4; j++) split_bf16(o[j], h[j], l[j]);
    __nv_bfloat162 hp0, hp1, lp0, lp1;
    hp0.x = h[0]; hp0.y = h[1]; hp1.x = h[2]; hp1.y = h[3];
    lp0.x = l[0]; lp0.y = l[1]; lp1.x = l[2]; lp1.y = l[3];
    *(__nv_bfloat162*)(phi + po)     = hp0;
    *(__nv_bfloat162*)(phi + po + 2) = hp1;
    *(__nv_bfloat162*)(plo + po)     = lp0;
    *(__nv_bfloat162*)(plo + po + 2) = lp1;
}

// ---------------------------------------------------------------------------
// low-rank gate
// ---------------------------------------------------------------------------
__global__ __launch_bounds__(256) void glow_kernel(
    const float* __restrict__ h, const float* __restrict__ Wgk1,
    float* __restrict__ glow)
{
    int idx = blockIdx.x * 256 + threadIdx.x;
    int m = idx >> 4;
    int r = idx & 15;
    const float* hr = h + (size_t)m * HS;
    float acc = 0.0f;
    #pragma unroll 8
    for (int k = 0; k < HS; k++)
        acc = fmaf(hr[k], Wgk1[(size_t)k * RLOW + r], acc);
    glow[idx] = acc;
}

__global__ __launch_bounds__(256) void glog_kernel(
    const float* __restrict__ glow, const float* __restrict__ Wgk2,
    const float* __restrict__ bgk2, float* __restrict__ glog)
{
    int idx = blockIdx.x * 256 + threadIdx.x;
    int m = idx >> 9;
    int n = idx & 511;
    const float* gr = glow + (size_t)m * RLOW;
    float acc = bgk2[n];
    #pragma unroll
    for (int r = 0; r < RLOW; r++)
        acc = fmaf(gr[r], Wgk2[(size_t)r * DKTOT + n], acc);
    glog[idx] = logsigmoidf_(acc) / GLN;
}

// ---------------------------------------------------------------------------
// GLA chunked attention (reads fused QKVG buffer, stride QS)
// ---------------------------------------------------------------------------
#define DKP 129
#define PE  65
#define GLA_SMEM_FLOATS (128*PE + 3*CH*DKP + 2*CH*PE)
#define GLA_SMEM_BYTES  (GLA_SMEM_FLOATS * 4)

__global__ __launch_bounds__(256) void gla_attn_kernel(
    const float* __restrict__ qkvg, const float* __restrict__ g,
    float* __restrict__ out)
{
    extern __shared__ float gla_sm[];
    const int ev = blockIdx.x;
    const int h  = blockIdx.y;
    const int b  = blockIdx.z;
    const int tid = threadIdx.x;

    float* S   = gla_sm;
    float* qe  = S  + 128 * PE;
    float* kd  = qe + CH * DKP;
    float* bc  = kd + CH * DKP;
    float* vs  = bc + CH * DKP;
    float* Am  = vs + CH * PE;

    for (int i = tid; i < 128 * PE; i += 256) S[i] = 0.0f;

    const float scale = rsqrtf((float)DK);
    const size_t rowb = (size_t)b * 2048;
    const float* qb = qkvg + rowb * QS + (size_t)h * DK;
    const float* kb = qb + 512;
    const float* gb = g + rowb * DKTOT + (size_t)h * DK;
    const float* vb = qkvg + rowb * QS + 1024 + (size_t)h * DV + (size_t)ev * 64;
    float* ob = out + rowb * DVTOT + (size_t)h * DV + (size_t)ev * 64;

    for (int n = 0; n < NCHUNK; n++) {
        const int t0 = n * CH;
        __syncthreads();

        if (tid < DK) {
            float run = 0.0f;
            #pragma unroll 8
            for (int c = 0; c < CH; c++) {
                run += gb[(size_t)(t0 + c) * DKTOT + tid];
                bc[c * DKP + tid] = run;
            }
        }
        for (int i = tid; i < CH * 64; i += 256) {
            int c = i >> 6, e = i & 63;
            vs[c * PE + e] = vb[(size_t)(t0 + c) * QS + e];
        }
        __syncthreads();

        for (int i = tid; i < CH * DK; i += 256) {
            int c = i >> 7, d = i & 127;
            float bv = bc[c * DKP + d];
            size_t gi = (size_t)(t0 + c) * QS + d;
            qe[c * DKP + d] = qb[gi] * expf(bv) * scale;
            kd[c * DKP + d] = kb[gi] * expf(-bv);
        }
        __syncthreads();

        {
            const int tc = (tid >> 4) * 4;
            const int ts = (tid & 15) * 4;
            float acc[4][4];
            #pragma unroll
            for (int i = 0; i < 4; i++)
                #pragma unroll
                for (int j = 0; j < 4; j++) acc[i][j] = 0.0f;
            for (int d = 0; d < DK; d++) {
                float a0 = qe[(tc + 0) * DKP + d];
                float a1 = qe[(tc + 1) * DKP + d];
                float a2 = qe[(tc + 2) * DKP + d];
                float a3 = qe[(tc + 3) * DKP + d];
                float b0 = kd[(ts + 0) * DKP + d];
                float b1 = kd[(ts + 1) * DKP + d];
                float b2 = kd[(ts + 2) * DKP + d];
                float b3 = kd[(ts + 3) * DKP + d];
                acc[0][0] = fmaf(a0, b0, acc[0][0]); acc[0][1] = fmaf(a0, b1, acc[0][1]);
                acc[0][2] = fmaf(a0, b2, acc[0][2]); acc[0][3] = fmaf(a0, b3, acc[0][3]);
                acc[1][0] = fmaf(a1, b0, acc[1][0]); acc[1][1] = fmaf(a1, b1, acc[1][1]);
                acc[1][2] = fmaf(a1, b2, acc[1][2]); acc[1][3] = fmaf(a1, b3, acc[1][3]);
                acc[2][0] = fmaf(a2, b0, acc[2][0]); acc[2][1] = fmaf(a2, b1, acc[2][1]);
                acc[2][2] = fmaf(a2, b2, acc[2][2]); acc[2][3] = fmaf(a2, b3, acc[2][3]);
                acc[3][0] = fmaf(a3, b0, acc[3][0]); acc[3][1] = fmaf(a3, b1, acc[3][1]);
                acc[3][2] = fmaf(a3, b2, acc[3][2]); acc[3][3] = fmaf(a3, b3, acc[3][3]);
            }
            #pragma unroll
            for (int i = 0; i < 4; i++)
                #pragma unroll
                for (int j = 0; j < 4; j++)
                    Am[(tc + i) * PE + ts + j] =
                        (tc + i >= ts + j) ? acc[i][j] : 0.0f;
        }
        __syncthreads();

        {
            const int tc = (tid >> 4) * 4;
            const int te = (tid & 15) * 4;
            float acc[4][4];
            #pragma unroll
            for (int i = 0; i < 4; i++)
                #pragma unroll
                for (int j = 0; j < 4; j++) acc[i][j] = 0.0f;
            for (int s = 0; s < CH; s++) {
                float a0 = Am[(tc + 0) * PE + s];
                float a1 = Am[(tc + 1) * PE + s];
                float a2 = Am[(tc + 2) * PE + s];
                float a3 = Am[(tc + 3) * PE + s];
                float v0 = vs[s * PE + te + 0];
                float v1 = vs[s * PE + te + 1];
                float v2 = vs[s * PE + te + 2];
                float v3 = vs[s * PE + te + 3];
                acc[0][0] = fmaf(a0, v0, acc[0][0]); acc[0][1] = fmaf(a0, v1, acc[0][1]);
                acc[0][2] = fmaf(a0, v2, acc[0][2]); acc[0][3] = fmaf(a0, v3, acc[0][3]);
                acc[1][0] = fmaf(a1, v0, acc[1][0]); acc[1][1] = fmaf(a1, v1, acc[1][1]);
                acc[1][2] = fmaf(a1, v2, acc[1][2]); acc[1][3] = fmaf(a1, v3, acc[1][3]);
                acc[2][0] = fmaf(a2, v0, acc[2][0]); acc[2][1] = fmaf(a2, v1, acc[2][1]);
                acc[2][2] = fmaf(a2, v2, acc[2][2]); acc[2][3] = fmaf(a2, v3, acc[2][3]);
                acc[3][0] = fmaf(a3, v0, acc[3][0]); acc[3][1] = fmaf(a3, v1, acc[3][1]);
                acc[3][2] = fmaf(a3, v2, acc[3][2]); acc[3][3] = fmaf(a3, v3, acc[3][3]);
            }
            for (int d = 0; d < DK; d++) {
                float a0 = qe[(tc + 0) * DKP + d];
                float a1 = qe[(tc + 1) * DKP + d];
                float a2 = qe[(tc + 2) * DKP + d];
                float a3 = qe[(tc + 3) * DKP + d];
                float s0 = S[d * PE + te + 0];
                float s1 = S[d * PE + te + 1];
                float s2 = S[d * PE + te + 2];
                float s3 = S[d * PE + te + 3];
                acc[0][0] = fmaf(a0, s0, acc[0][0]); acc[0][1] = fmaf(a0, s1, acc[0][1]);
                acc[0][2] = fmaf(a0, s2, acc[0][2]); acc[0][3] = fmaf(a0, s3, acc[0][3]);
                acc[1][0] = fmaf(a1, s0, acc[1][0]); acc[1][1] = fmaf(a1, s1, acc[1][1]);
                acc[1][2] = fmaf(a1, s2, acc[1][2]); acc[1][3] = fmaf(a1, s3, acc[1][3]);
                acc[2][0] = fmaf(a2, s0, acc[2][0]); acc[2][1] = fmaf(a2, s1, acc[2][1]);
                acc[2][2] = fmaf(a2, s2, acc[2][2]); acc[2][3] = fmaf(a2, s3, acc[2][3]);
                acc[3][0] = fmaf(a3, s0, acc[3][0]); acc[3][1] = fmaf(a3, s1, acc[3][1]);
                acc[3][2] = fmaf(a3, s2, acc[3][2]); acc[3][3] = fmaf(a3, s3, acc[3][3]);
            }
            #pragma unroll
            for (int i = 0; i < 4; i++)
                #pragma unroll
                for (int j = 0; j < 4; j++)
                    ob[(size_t)(t0 + tc + i) * DVTOT + te + j] = acc[i][j];
        }
        __syncthreads();

        {
            const int td = (tid & 31) * 4;
            const int te = (tid >> 5) * 8;
            float ex[4];
            #pragma unroll
            for (int i = 0; i < 4; i++) ex[i] = expf(bc[63 * DKP + td + i]);
            float acc[4][8];
            #pragma unroll
            for (int i = 0; i < 4; i++)
                #pragma unroll
                for (int j = 0; j < 8; j++)
                    acc[i][j] = S[(td + i) * PE + te + j];
            for (int c = 0; c < CH; c++) {
                float k0 = kd[c * DKP + td + 0];
                float k1 = kd[c * DKP + td + 1];
                float k2 = kd[c * DKP + td + 2];
                float k3 = kd[c * DKP + td + 3];
                #pragma unroll
                for (int j = 0; j < 8; j++) {
                    float vv = vs[c * PE + te + j];
                    acc[0][j] = fmaf(k0, vv, acc[0][j]);
                    acc[1][j] = fmaf(k1, vv, acc[1][j]);
                    acc[2][j] = fmaf(k2, vv, acc[2][j]);
                    acc[3][j] = fmaf(k3, vv, acc[3][j]);
                }
            }
            #pragma unroll
            for (int i = 0; i < 4; i++)
                #pragma unroll
                for (int j = 0; j < 8; j++)
                    S[(td + i) * PE + te + j] = ex[i] * acc[i][j];
        }
    }
}

// ---------------------------------------------------------------------------
// per-head RMSNorm + swish gate (gate read from fused QKVG) -> bf16 planes
// ---------------------------------------------------------------------------
__global__ __launch_bounds__(256) void gnorm_gate_kernel(
    const float* __restrict__ o, const float* __restrict__ qkvg,
    const float* __restrict__ w,
    __nv_bfloat16* __restrict__ phi, __nv_bfloat16* __restrict__ plo)
{
    __shared__ float red8[8];
    size_t idx = (size_t)blockIdx.x * 256 + threadIdx.x;
    int token = blockIdx.x >> 2;
    int h = blockIdx.x & 3;
    float val = o[idx];
    float tot = block_reduce_sum_256(val * val, red8);
    float r = rsqrtf(tot / (float)DV + EPS);
    float gv = qkvg[(size_t)token * QS + 2048 + h * 256 + threadIdx.x];
    float y = val * r * w[threadIdx.x] * gv * sigmoidf_(gv);
    __nv_bfloat16 hh, ll;
    split_bf16(y, hh, ll);
    phi[idx] = hh;
    plo[idx] = ll;
}

// ---------------------------------------------------------------------------
// Launch
// ---------------------------------------------------------------------------
extern "C" void kernel_launch(void* const* d_in, const int* in_sizes, int n_in,
                              void* d_out, int out_size)
{
    (void)in_sizes; (void)n_in; (void)out_size;
    const float* x         = (const float*)d_in[0];
    const float* attn_w    = (const float*)d_in[1];
    const float* Wq        = (const float*)d_in[2];
    const float* Wk        = (const float*)d_in[3];
    const float* Wv        = (const float*)d_in[4];
    const float* Wg        = (const float*)d_in[5];
    const float* Wgk1      = (const float*)d_in[6];
    const float* Wgk2      = (const float*)d_in[7];
    const float* bgk2      = (const float*)d_in[8];
    const float* gnorm_w   = (const float*)d_in[9];
    const float* Wo        = (const float*)d_in[10];
    const float* mlp_w     = (const float*)d_in[11];
    const float* W_gate    = (const float*)d_in[12];
    const float* W_up      = (const float*)d_in[13];
    const float* W_down    = (const float*)d_in[14];
    float* out             = (float*)d_out;

    float* sc = nullptr;
    cudaGetSymbolAddress((void**)&sc, g_scratch);
    __nv_bfloat16* wb = nullptr;
    cudaGetSymbolAddress((void**)&wb, g_wbf);
    __nv_bfloat16* act = nullptr;
    cudaGetSymbolAddress((void**)&act, g_act);
    __nv_bfloat16* upa = nullptr;
    cudaGetSymbolAddress((void**)&upa, g_upa);

    float* h_    = sc + OFF_H;
    float* qkvg_ = sc + OFF_QKVG;
    float* glow_ = sc + OFF_GLOW;
    float* glog_ = sc + OFF_GLOG;
    float* gla_  = sc + OFF_GLA;
    float* up_   = sc + OFF_UP;
    float* x2_   = qkvg_;           // qkvg dead after gnorm_gate

    __nv_bfloat16* actHi = act;
    __nv_bfloat16* actLo = act + ACT_PLANE;
    __nv_bfloat16* upHi  = upa;
    __nv_bfloat16* upLo  = upa + UPA_PLANE;

    __nv_bfloat16* wQKVGhi = wb + OW_QKVG;
    __nv_bfloat16* wQKVGlo = wQKVGhi + 3145728ull;

    cudaFuncSetAttribute(gla_attn_kernel,
                         cudaFuncAttributeMaxDynamicSharedMemorySize, GLA_SMEM_BYTES);
    cudaFuncSetAttribute(hgemm_kernel<0>,
                         cudaFuncAttributeMaxDynamicSharedMemorySize, HG_SMEM);
    cudaFuncSetAttribute(hgemm_kernel<1>,
                         cudaFuncAttributeMaxDynamicSharedMemorySize, HG_SMEM);
    cudaFuncSetAttribute(hgemm_kernel<2>,
                         cudaFuncAttributeMaxDynamicSharedMemorySize, HG_SMEM);

    dim3 tb(32, 8);
    wconv_kernel<<<dim3(HS/32, DKTOT/32), tb>>>(Wq, wQKVGhi,              wQKVGlo,              HS, DKTOT);
    wconv_kernel<<<dim3(HS/32, DKTOT/32), tb>>>(Wk, wQKVGhi +  512ull*HS, wQKVGlo +  512ull*HS, HS, DKTOT);
    wconv_kernel<<<dim3(HS/32, DVTOT/32), tb>>>(Wv, wQKVGhi + 1024ull*HS, wQKVGlo + 1024ull*HS, HS, DVTOT);
    wconv_kernel<<<dim3(HS/32, DVTOT/32), tb>>>(Wg, wQKVGhi + 2048ull*HS, wQKVGlo + 2048ull*HS, HS, DVTOT);
    wconv_kernel<<<dim3(DVTOT/32, HS/32), tb>>>(Wo,     wb + OW_O,    wb + OW_O    + 1048576, DVTOT, HS);
    wconv_kernel<<<dim3(HS/32, IMLP/32),  tb>>>(W_gate, wb + OW_GATE, wb + OW_GATE + 2883584, HS,   IMLP);
    wconv_kernel<<<dim3(HS/32, IMLP/32),  tb>>>(W_up,   wb + OW_UPW,  wb + OW_UPW  + 2883584, HS,   IMLP);
    wconv_kernel<<<dim3(IMLP/32, HS/32),  tb>>>(W_down, wb + OW_DOWN, wb + OW_DOWN + 2883584, IMLP, HS);

    // 1. h = rms(x)
    rmsnorm1024_kernel<<<NTOK, 256>>>(x, attn_w, h_, actHi, actLo);

    // 2. fused QKVG projection (N=3072)
    hgemm_kernel<0><<<dim3(QS/128, NTOK/128), 256, HG_SMEM>>>(
        actHi, actLo, wQKVGhi, wQKVGlo, qkvg_, nullptr, nullptr, nullptr, QS, HS);

    // 3. low-rank gate logits
    glow_kernel<<<(NTOK * RLOW) / 256, 256>>>(h_, Wgk1, glow_);
    glog_kernel<<<(NTOK * DKTOT) / 256, 256>>>(glow_, Wgk2, bgk2, glog_);

    // 4. chunked GLA
    gla_attn_kernel<<<dim3(4, NH, 4), 256, GLA_SMEM_BYTES>>>(qkvg_, glog_, gla_);

    // 5. per-head rmsnorm + swish gate -> og planes
    gnorm_gate_kernel<<<NTOK * NH, 256>>>(gla_, qkvg_, gnorm_w, actHi, actLo);

    // 6. x2 = og@Wo + x
    hgemm_kernel<1><<<dim3(HS/128, NTOK/128), 256, HG_SMEM>>>(
        actHi, actLo, wb + OW_O, wb + OW_O + 1048576, x2_, x, nullptr, nullptr, HS, DVTOT);

    // 7. mlp norm -> n planes
    rmsnorm1024_kernel<<<NTOK, 256>>>(x2_, mlp_w, nullptr, actHi, actLo);

    // 8. SwiGLU
    hgemm_kernel<0><<<dim3(IMLP/128, NTOK/128), 256, HG_SMEM>>>(
        actHi, actLo, wb + OW_UPW, wb + OW_UPW + 2883584, up_, nullptr, nullptr, nullptr, IMLP, HS);
    hgemm_kernel<2><<<dim3(IMLP/128, NTOK/128), 256, HG_SMEM>>>(
        actHi, actLo, wb + OW_GATE, wb + OW_GATE + 2883584, nullptr, up_, upHi, upLo, IMLP, HS);

    // 9. out = up@W_down + x2
    hgemm_kernel<1><<<dim3(HS/128, NTOK/128), 256, HG_SMEM>>>(
        upHi, upLo, wb + OW_DOWN, wb + OW_DOWN + 2883584, out, x2_, nullptr, nullptr, HS, IMLP);
}

// round 8
// speedup vs baseline: 2.5526x; 1.0799x over previous
#include <cuda_runtime.h>
#include <cuda_bf16.h>
#include <math.h>
#include <stdint.h>

// ---------------------------------------------------------------------------
// Problem constants
// ---------------------------------------------------------------------------
#define NTOK   8192
#define HS     1024
#define DKTOT  512
#define DVTOT  1024
#define NH     4
#define DK     128
#define DV     256
#define CH     64
#define NCHUNK 32
#define RLOW   16
#define IMLP   2816
#define EPS    1e-6f
#define GLN    16.0f
#define QS     3072            // fused QKVG row stride

// ---------------------------------------------------------------------------
// fp32 scratch
// ---------------------------------------------------------------------------
#define OFF_H     0ull
#define OFF_QKVG  (OFF_H    + 8388608ull)
#define OFF_GLOW  (OFF_QKVG + 25165824ull)
#define OFF_GLOG  (OFF_GLOW + 131072ull)
#define OFF_GLA   (OFF_GLOG + 4194304ull)
#define OFF_UP    (OFF_GLA  + 8388608ull)
#define SCRATCH_FLOATS (OFF_UP + 23068672ull)

__device__ float g_scratch[SCRATCH_FLOATS];

// bf16 weights, transposed [N][K], hi plane then lo plane per weight group
#define OW_QKVG  0ull
#define OW_O     (OW_QKVG + 6291456ull)
#define OW_GATE  (OW_O    + 2097152ull)
#define OW_UPW   (OW_GATE + 5767168ull)
#define OW_DOWN  (OW_UPW  + 5767168ull)
#define WBF_ELEMS (OW_DOWN + 5767168ull)

__device__ __align__(16) __nv_bfloat16 g_wbf[WBF_ELEMS];

// bf16 activation planes
#define ACT_PLANE 8388608ull
__device__ __align__(16) __nv_bfloat16 g_act[2ull * ACT_PLANE];
#define UPA_PLANE 23068672ull
__device__ __align__(16) __nv_bfloat16 g_upa[2ull * UPA_PLANE];

// ---------------------------------------------------------------------------
// math utils
// ---------------------------------------------------------------------------
__device__ __forceinline__ float sigmoidf_(float x) { return 1.0f / (1.0f + expf(-x)); }
__device__ __forceinline__ float logsigmoidf_(float x) {
    return fminf(x, 0.0f) - log1pf(expf(-fabsf(x)));
}
__device__ __forceinline__ float block_reduce_sum_256(float v, float* red8) {
    #pragma unroll
    for (int o = 16; o > 0; o >>= 1) v += __shfl_xor_sync(0xffffffffu, v, o);
    if ((threadIdx.x & 31) == 0) red8[threadIdx.x >> 5] = v;
    __syncthreads();
    float s;
    if (threadIdx.x < 8) {
        s = red8[threadIdx.x];
        #pragma unroll
        for (int o = 4; o > 0; o >>= 1) s += __shfl_xor_sync(0xffu, s, o);
        if (threadIdx.x == 0) red8[0] = s;
    }
    __syncthreads();
    return red8[0];
}
__device__ __forceinline__ void split_bf16(float v, __nv_bfloat16& h, __nv_bfloat16& l) {
    h = __float2bfloat16(v);
    l = __float2bfloat16(v - __bfloat162float(h));
}

// ---------------------------------------------------------------------------
// PTX helpers (sm_100-safe)
// ---------------------------------------------------------------------------
__device__ __forceinline__ uint32_t smem_u32(const void* p) {
    uint32_t a;
    asm("{ .reg .u64 t; cvta.to.shared.u64 t, %1; cvt.u32.u64 %0, t; }"
        : "=r"(a) : "l"(p));
    return a;
}
__device__ __forceinline__ void cpasync16(uint32_t s, const void* g) {
    asm volatile("cp.async.cg.shared.global [%0], [%1], 16;" :: "r"(s), "l"(g));
}
#define CP_COMMIT() asm volatile("cp.async.commit_group;" ::: "memory")
#define CP_WAIT1()  asm volatile("cp.async.wait_group 1;" ::: "memory")
#define CP_WAIT0()  asm volatile("cp.async.wait_group 0;" ::: "memory")

#define LDSM4(r0, r1, r2, r3, a) \
    asm volatile("ldmatrix.sync.aligned.m8n8.x4.shared.b16 {%0,%1,%2,%3}, [%4];" \
        : "=r"(r0), "=r"(r1), "=r"(r2), "=r"(r3) : "r"(a))

#define MMA16816(d, a, b) \
    asm volatile("mma.sync.aligned.m16n8k16.row.col.f32.bf16.bf16.f32 " \
        "{%0,%1,%2,%3}, {%4,%5,%6,%7}, {%8,%9}, {%0,%1,%2,%3};" \
        : "+f"((d)[0]), "+f"((d)[1]), "+f"((d)[2]), "+f"((d)[3]) \
        : "r"((a)[0]), "r"((a)[1]), "r"((a)[2]), "r"((a)[3]), \
          "r"((b)[0]), "r"((b)[1]))

// ---------------------------------------------------------------------------
// weight transpose + split
// ---------------------------------------------------------------------------
__global__ void wconv_kernel(const float* __restrict__ W,
                             __nv_bfloat16* __restrict__ hi,
                             __nv_bfloat16* __restrict__ lo,
                             int K, int N)
{
    __shared__ float t[32][33];
    int k0 = blockIdx.x * 32, n0 = blockIdx.y * 32;
    int tx = threadIdx.x, ty = threadIdx.y;
    #pragma unroll
    for (int i = 0; i < 4; i++)
        t[ty + i * 8][tx] = W[(size_t)(k0 + ty + i * 8) * N + n0 + tx];
    __syncthreads();
    #pragma unroll
    for (int i = 0; i < 4; i++) {
        float v = t[tx][ty + i * 8];
        __nv_bfloat16 h, l;
        split_bf16(v, h, l);
        size_t o = (size_t)(n0 + ty + i * 8) * K + k0 + tx;
        hi[o] = h;
        lo[o] = l;
    }
}

// ---------------------------------------------------------------------------
// HGEMM v4: 128x128x32, 3-stage cp.async, 1 sync/iter, compact XOR swizzle,
// 2 CTAs/SM, 3-chain bf16 split, chain-outermost MMA issue order (8
// independent accumulators between same-acc reuse).
// EPI: 0 C=acc; 1 C=acc+E; 2 planes=split(silu(acc)*E)
// ---------------------------------------------------------------------------
#define SO(row, c) ((uint32_t)(((row) << 6) + ((((c) ^ (((row) >> 1) & 3))) << 4)))
#define PLANE_B 8192
#define STAGE_B (4 * PLANE_B)
#define HG_SMEM (3 * STAGE_B)

template <int EPI>
__global__ __launch_bounds__(256, 2) void hgemm_kernel(
    const __nv_bfloat16* __restrict__ Ahi, const __nv_bfloat16* __restrict__ Alo,
    const __nv_bfloat16* __restrict__ Bhi, const __nv_bfloat16* __restrict__ Blo,
    float* __restrict__ C, const float* __restrict__ E,
    __nv_bfloat16* __restrict__ Phi, __nv_bfloat16* __restrict__ Plo,
    int N, int K)
{
    extern __shared__ char sm[];
    const uint32_t smb = smem_u32(sm);
    const int tid  = threadIdx.x;
    const int lane = tid & 31;
    const int wid  = tid >> 5;
    const int wm   = (wid >> 1) * 32;
    const int wn   = (wid & 1) * 64;
    const int m0   = blockIdx.y * 128;
    const int n0   = blockIdx.x * 128;

    float acc[2][8][4];
    #pragma unroll
    for (int mt = 0; mt < 2; mt++)
        #pragma unroll
        for (int nt = 0; nt < 8; nt++)
            #pragma unroll
            for (int j = 0; j < 4; j++) acc[mt][nt][j] = 0.0f;

    const int nkb = K / 32;

    auto stage_load = [&](int st) {
        const uint32_t sb = smb + (st % 3) * STAGE_B;
        const int k0 = st * 32;
        #pragma unroll
        for (int half = 0; half < 2; half++) {
            int ch = tid + half * 256;
            int row = ch >> 2, c = ch & 3;
            uint32_t so = SO(row, c);
            size_t ga = (size_t)(m0 + row) * K + k0 + c * 8;
            size_t gb = (size_t)(n0 + row) * K + k0 + c * 8;
            cpasync16(sb + 0 * PLANE_B + so, Ahi + ga);
            cpasync16(sb + 1 * PLANE_B + so, Alo + ga);
            cpasync16(sb + 2 * PLANE_B + so, Bhi + gb);
            cpasync16(sb + 3 * PLANE_B + so, Blo + gb);
        }
    };

    stage_load(0); CP_COMMIT();
    stage_load(1); CP_COMMIT();

    for (int s = 0; s < nkb; s++) {
        if (s + 1 < nkb) CP_WAIT1(); else CP_WAIT0();
        __syncthreads();
        if (s + 2 < nkb) { stage_load(s + 2); CP_COMMIT(); }

        const uint32_t sb = smb + (s % 3) * STAGE_B;
        #pragma unroll
        for (int kk = 0; kk < 2; kk++) {
            uint32_t ah[2][4], al[2][4];
            #pragma unroll
            for (int mt = 0; mt < 2; mt++) {
                int row = wm + mt * 16 + (lane & 15);
                int c = kk * 2 + (lane >> 4);
                uint32_t so = SO(row, c);
                LDSM4(ah[mt][0], ah[mt][1], ah[mt][2], ah[mt][3], sb + 0 * PLANE_B + so);
                LDSM4(al[mt][0], al[mt][1], al[mt][2], al[mt][3], sb + 1 * PLANE_B + so);
            }
            // process n-groups in pairs; chain-outermost over 8 accumulators
            #pragma unroll
            for (int gp = 0; gp < 2; gp++) {
                uint32_t bh[4][2], bl[4][2];
                #pragma unroll
                for (int g01 = 0; g01 < 2; g01++) {
                    int g = gp * 2 + g01;
                    int row = wn + g * 16 + (lane & 7) + ((lane >> 4) << 3);
                    int c = kk * 2 + ((lane >> 3) & 1);
                    uint32_t so = SO(row, c);
                    LDSM4(bh[g01*2][0], bh[g01*2][1], bh[g01*2+1][0], bh[g01*2+1][1],
                          sb + 2 * PLANE_B + so);
                    LDSM4(bl[g01*2][0], bl[g01*2][1], bl[g01*2+1][0], bl[g01*2+1][1],
                          sb + 3 * PLANE_B + so);
                }
                // chain 0: ah*bh over all 8 accs
                #pragma unroll
                for (int q = 0; q < 4; q++)
                    #pragma unroll
                    for (int mt = 0; mt < 2; mt++)
                        MMA16816(acc[mt][gp * 4 + q], ah[mt], bh[q]);
                // chain 1: ah*bl
                #pragma unroll
                for (int q = 0; q < 4; q++)
                    #pragma unroll
                    for (int mt = 0; mt < 2; mt++)
                        MMA16816(acc[mt][gp * 4 + q], ah[mt], bl[q]);
                // chain 2: al*bh
                #pragma unroll
                for (int q = 0; q < 4; q++)
                    #pragma unroll
                    for (int mt = 0; mt < 2; mt++)
                        MMA16816(acc[mt][gp * 4 + q], al[mt], bh[q]);
            }
        }
    }

    // epilogue
    const int r0 = lane >> 2;
    const int cc = (lane & 3) * 2;
    #pragma unroll
    for (int mt = 0; mt < 2; mt++)
        #pragma unroll
        for (int nt = 0; nt < 8; nt++) {
            int grow = m0 + wm + mt * 16 + r0;
            int gcol = n0 + wn + nt * 8 + cc;
            #pragma unroll
            for (int hrow = 0; hrow < 2; hrow++) {
                size_t off = (size_t)(grow + hrow * 8) * N + gcol;
                float v0 = acc[mt][nt][hrow * 2 + 0];
                float v1 = acc[mt][nt][hrow * 2 + 1];
                if (EPI == 0) {
                    *(float2*)(C + off) = make_float2(v0, v1);
                } else if (EPI == 1) {
                    float2 e = *(const float2*)(E + off);
                    *(float2*)(C + off) = make_float2(v0 + e.x, v1 + e.y);
                } else {
                    float2 e = *(const float2*)(E + off);
                    v0 = v0 * sigmoidf_(v0) * e.x;
                    v1 = v1 * sigmoidf_(v1) * e.y;
                    __nv_bfloat16 h0, l0, h1, l1;
                    split_bf16(v0, h0, l0);
                    split_bf16(v1, h1, l1);
                    __nv_bfloat162 hp, lp;
                    hp.x = h0; hp.y = h1; lp.x = l0; lp.y = l1;
                    *(__nv_bfloat162*)(Phi + off) = hp;
                    *(__nv_bfloat162*)(Plo + off) = lp;
                }
            }
        }
}

// ---------------------------------------------------------------------------
// RMSNorm over 1024-wide rows; optional fp32 out + bf16 planes
// ---------------------------------------------------------------------------
__global__ __launch_bounds__(256) void rmsnorm1024_kernel(
    const float* __restrict__ x, const float* __restrict__ w,
    float* __restrict__ y,
    __nv_bfloat16* __restrict__ phi, __nv_bfloat16* __restrict__ plo)
{
    __shared__ float red8[8];
    const size_t row = blockIdx.x;
    const float4* xr = (const float4*)(x + row * (size_t)HS);
    float4 v = xr[threadIdx.x];
    float ss = v.x * v.x + v.y * v.y + v.z * v.z + v.w * v.w;
    float tot = block_reduce_sum_256(ss, red8);
    float r = rsqrtf(tot / (float)HS + EPS);
    const float4* wr = (const float4*)w;
    float4 wv = wr[threadIdx.x];
    float o[4];
    o[0] = v.x * r * wv.x; o[1] = v.y * r * wv.y;
    o[2] = v.z * r * wv.z; o[3] = v.w * r * wv.w;
    if (y)
        ((float4*)(y + row * (size_t)HS))[threadIdx.x] =
            make_float4(o[0], o[1], o[2], o[3]);
    size_t po = row * (size_t)HS + threadIdx.x * 4;
    __nv_bfloat16 h[4], l[4];
    #pragma unroll
    for (int j = 0; j < 4; j++) split_bf16(o[j], h[j], l[j]);
    __nv_bfloat162 hp0, hp1, lp0, lp1;
    hp0.x = h[0]; hp0.y = h[1]; hp1.x = h[2]; hp1.y = h[3];
    lp0.x = l[0]; lp0.y = l[1]; lp1.x = l[2]; lp1.y = l[3];
    *(__nv_bfloat162*)(phi + po)     = hp0;
    *(__nv_bfloat162*)(phi + po + 2) = hp1;
    *(__nv_bfloat162*)(plo + po)     = lp0;
    *(__nv_bfloat162*)(plo + po + 2) = lp1;
}

// ---------------------------------------------------------------------------
// low-rank gate
// ---------------------------------------------------------------------------
__global__ __launch_bounds__(256) void glow_kernel(
    const float* __restrict__ h, const float* __restrict__ Wgk1,
    float* __restrict__ glow)
{
    int idx = blockIdx.x * 256 + threadIdx.x;
    int m = idx >> 4;
    int r = idx & 15;
    const float* hr = h + (size_t)m * HS;
    float acc = 0.0f;
    #pragma unroll 8
    for (int k = 0; k < HS; k++)
        acc = fmaf(hr[k], Wgk1[(size_t)k * RLOW + r], acc);
    glow[idx] = acc;
}

__global__ __launch_bounds__(256) void glog_kernel(
    const float* __restrict__ glow, const float* __restrict__ Wgk2,
    const float* __restrict__ bgk2, float* __restrict__ glog)
{
    int idx = blockIdx.x * 256 + threadIdx.x;
    int m = idx >> 9;
    int n = idx & 511;
    const float* gr = glow + (size_t)m * RLOW;
    float acc = bgk2[n];
    #pragma unroll
    for (int r = 0; r < RLOW; r++)
        acc = fmaf(gr[r], Wgk2[(size_t)r * DKTOT + n], acc);
    glog[idx] = logsigmoidf_(acc) / GLN;
}

// ---------------------------------------------------------------------------
// GLA chunked attention, 8-way dv split (32-wide), 128 CTAs.
// ---------------------------------------------------------------------------
#define DKP 129
#define PE  65      // Am row stride
#define PV  33      // vs / S row stride (32-wide ev block)
#define GLA_SMEM_FLOATS (128*PV + 3*CH*DKP + CH*PV + CH*PE)
#define GLA_SMEM_BYTES  (GLA_SMEM_FLOATS * 4)

__global__ __launch_bounds__(256) void gla_attn_kernel(
    const float* __restrict__ qkvg, const float* __restrict__ g,
    float* __restrict__ out)
{
    extern __shared__ float gla_sm[];
    const int ev = blockIdx.x;      // 0..7, 32-wide dv block
    const int h  = blockIdx.y;
    const int b  = blockIdx.z;
    const int tid = threadIdx.x;

    float* S   = gla_sm;            // [128][PV]
    float* qe  = S  + 128 * PV;     // [64][DKP]
    float* kd  = qe + CH * DKP;     // [64][DKP]
    float* bc  = kd + CH * DKP;     // [64][DKP]
    float* vs  = bc + CH * DKP;     // [64][PV]
    float* Am  = vs + CH * PV;      // [64][PE]

    for (int i = tid; i < 128 * PV; i += 256) S[i] = 0.0f;

    const float scale = rsqrtf((float)DK);
    const size_t rowb = (size_t)b * 2048;
    const float* qb = qkvg + rowb * QS + (size_t)h * DK;
    const float* kb = qb + 512;
    const float* gb = g + rowb * DKTOT + (size_t)h * DK;
    const float* vb = qkvg + rowb * QS + 1024 + (size_t)h * DV + (size_t)ev * 32;
    float* ob = out + rowb * DVTOT + (size_t)h * DV + (size_t)ev * 32;

    for (int n = 0; n < NCHUNK; n++) {
        const int t0 = n * CH;
        __syncthreads();

        if (tid < DK) {
            float run = 0.0f;
            #pragma unroll 8
            for (int c = 0; c < CH; c++) {
                run += gb[(size_t)(t0 + c) * DKTOT + tid];
                bc[c * DKP + tid] = run;
            }
        }
        for (int i = tid; i < CH * 32; i += 256) {
            int c = i >> 5, e = i & 31;
            vs[c * PV + e] = vb[(size_t)(t0 + c) * QS + e];
        }
        __syncthreads();

        for (int i = tid; i < CH * DK; i += 256) {
            int c = i >> 7, d = i & 127;
            float bv = bc[c * DKP + d];
            size_t gi = (size_t)(t0 + c) * QS + d;
            qe[c * DKP + d] = qb[gi] * expf(bv) * scale;
            kd[c * DKP + d] = kb[gi] * expf(-bv);
        }
        __syncthreads();

        // A[c,s] = qe[c,:].kd[s,:]  (masked c>=s), full 64x64
        {
            const int tc = (tid >> 4) * 4;
            const int ts = (tid & 15) * 4;
            float acc[4][4];
            #pragma unroll
            for (int i = 0; i < 4; i++)
                #pragma unroll
                for (int j = 0; j < 4; j++) acc[i][j] = 0.0f;
            for (int d = 0; d < DK; d++) {
                float a0 = qe[(tc + 0) * DKP + d];
                float a1 = qe[(tc + 1) * DKP + d];
                float a2 = qe[(tc + 2) * DKP + d];
                float a3 = qe[(tc + 3) * DKP + d];
                float b0 = kd[(ts + 0) * DKP + d];
                float b1 = kd[(ts + 1) * DKP + d];
                float b2 = kd[(ts + 2) * DKP + d];
                float b3 = kd[(ts + 3) * DKP + d];
                acc[0][0] = fmaf(a0, b0, acc[0][0]); acc[0][1] = fmaf(a0, b1, acc[0][1]);
                acc[0][2] = fmaf(a0, b2, acc[0][2]); acc[0][3] = fmaf(a0, b3, acc[0][3]);
                acc[1][0] = fmaf(a1, b0, acc[1][0]); acc[1][1] = fmaf(a1, b1, acc[1][1]);
                acc[1][2] = fmaf(a1, b2, acc[1][2]); acc[1][3] = fmaf(a1, b3, acc[1][3]);
                acc[2][0] = fmaf(a2, b0, acc[2][0]); acc[2][1] = fmaf(a2, b1, acc[2][1]);
                acc[2][2] = fmaf(a2, b2, acc[2][2]); acc[2][3] = fmaf(a2, b3, acc[2][3]);
                acc[3][0] = fmaf(a3, b0, acc[3][0]); acc[3][1] = fmaf(a3, b1, acc[3][1]);
                acc[3][2] = fmaf(a3, b2, acc[3][2]); acc[3][3] = fmaf(a3, b3, acc[3][3]);
            }
            #pragma unroll
            for (int i = 0; i < 4; i++)
                #pragma unroll
                for (int j = 0; j < 4; j++)
                    Am[(tc + i) * PE + ts + j] =
                        (tc + i >= ts + j) ? acc[i][j] : 0.0f;
        }
        __syncthreads();

        // o[c,e] = A[c,:]@v[:,e] + qe[c,:]@S[:,e], e in 32-wide block
        {
            const int tc = (tid >> 4) * 4;       // 0..60
            const int te = (tid & 15) * 2;       // 0..30
            float acc[4][2];
            #pragma unroll
            for (int i = 0; i < 4; i++) { acc[i][0] = 0.0f; acc[i][1] = 0.0f; }
            for (int s = 0; s < CH; s++) {
                float v0 = vs[s * PV + te + 0];
                float v1 = vs[s * PV + te + 1];
                #pragma unroll
                for (int i = 0; i < 4; i++) {
                    float a = Am[(tc + i) * PE + s];
                    acc[i][0] = fmaf(a, v0, acc[i][0]);
                    acc[i][1] = fmaf(a, v1, acc[i][1]);
                }
            }
            for (int d = 0; d < DK; d++) {
                float s0 = S[d * PV + te + 0];
                float s1 = S[d * PV + te + 1];
                #pragma unroll
                for (int i = 0; i < 4; i++) {
                    float a = qe[(tc + i) * DKP + d];
                    acc[i][0] = fmaf(a, s0, acc[i][0]);
                    acc[i][1] = fmaf(a, s1, acc[i][1]);
                }
            }
            #pragma unroll
            for (int i = 0; i < 4; i++) {
                float* orow = ob + (size_t)(t0 + tc + i) * DVTOT + te;
                orow[0] = acc[i][0];
                orow[1] = acc[i][1];
            }
        }
        __syncthreads();

        // S[d,e] = exp(blast[d]) * (S[d,e] + sum_c kd[c,d]*v[c,e])
        {
            const int td = (tid & 31) * 4;       // 0..124
            const int te = (tid >> 5) * 4;       // 0..28
            float ex[4];
            #pragma unroll
            for (int i = 0; i < 4; i++) ex[i] = expf(bc[63 * DKP + td + i]);
            float acc[4][4];
            #pragma unroll
            for (int i = 0; i < 4; i++)
                #pragma unroll
                for (int j = 0; j < 4; j++)
                    acc[i][j] = S[(td + i) * PV + te + j];
            for (int c = 0; c < CH; c++) {
                float k0 = kd[c * DKP + td + 0];
                float k1 = kd[c * DKP + td + 1];
                float k2 = kd[c * DKP + td + 2];
                float k3 = kd[c * DKP + td + 3];
                #pragma unroll
                for (int j = 0; j < 4; j++) {
                    float vv = vs[c * PV + te + j];
                    acc[0][j] = fmaf(k0, vv, acc[0][j]);
                    acc[1][j] = fmaf(k1, vv, acc[1][j]);
                    acc[2][j] = fmaf(k2, vv, acc[2][j]);
                    acc[3][j] = fmaf(k3, vv, acc[3][j]);
                }
            }
            #pragma unroll
            for (int i = 0; i < 4; i++)
                #pragma unroll
                for (int j = 0; j < 4; j++)
                    S[(td + i) * PV + te + j] = ex[i] * acc[i][j];
        }
    }
}

// ---------------------------------------------------------------------------
// per-head RMSNorm + swish gate (gate read from fused QKVG) -> bf16 planes
// ---------------------------------------------------------------------------
__global__ __launch_bounds__(256) void gnorm_gate_kernel(
    const float* __restrict__ o, const float* __restrict__ qkvg,
    const float* __restrict__ w,
    __nv_bfloat16* __restrict__ phi, __nv_bfloat16* __restrict__ plo)
{
    __shared__ float red8[8];
    size_t idx = (size_t)blockIdx.x * 256 + threadIdx.x;
    int token = blockIdx.x >> 2;
    int h = blockIdx.x & 3;
    float val = o[idx];
    float tot = block_reduce_sum_256(val * val, red8);
    float r = rsqrtf(tot / (float)DV + EPS);
    float gv = qkvg[(size_t)token * QS + 2048 + h * 256 + threadIdx.x];
    float y = val * r * w[threadIdx.x] * gv * sigmoidf_(gv);
    __nv_bfloat16 hh, ll;
    split_bf16(y, hh, ll);
    phi[idx] = hh;
    plo[idx] = ll;
}

// ---------------------------------------------------------------------------
// Launch
// ---------------------------------------------------------------------------
extern "C" void kernel_launch(void* const* d_in, const int* in_sizes, int n_in,
                              void* d_out, int out_size)
{
    (void)in_sizes; (void)n_in; (void)out_size;
    const float* x         = (const float*)d_in[0];
    const float* attn_w    = (const float*)d_in[1];
    const float* Wq        = (const float*)d_in[2];
    const float* Wk        = (const float*)d_in[3];
    const float* Wv        = (const float*)d_in[4];
    const float* Wg        = (const float*)d_in[5];
    const float* Wgk1      = (const float*)d_in[6];
    const float* Wgk2      = (const float*)d_in[7];
    const float* bgk2      = (const float*)d_in[8];
    const float* gnorm_w   = (const float*)d_in[9];
    const float* Wo        = (const float*)d_in[10];
    const float* mlp_w     = (const float*)d_in[11];
    const float* W_gate    = (const float*)d_in[12];
    const float* W_up      = (const float*)d_in[13];
    const float* W_down    = (const float*)d_in[14];
    float* out             = (float*)d_out;

    float* sc = nullptr;
    cudaGetSymbolAddress((void**)&sc, g_scratch);
    __nv_bfloat16* wb = nullptr;
    cudaGetSymbolAddress((void**)&wb, g_wbf);
    __nv_bfloat16* act = nullptr;
    cudaGetSymbolAddress((void**)&act, g_act);
    __nv_bfloat16* upa = nullptr;
    cudaGetSymbolAddress((void**)&upa, g_upa);

    float* h_    = sc + OFF_H;
    float* qkvg_ = sc + OFF_QKVG;
    float* glow_ = sc + OFF_GLOW;
    float* glog_ = sc + OFF_GLOG;
    float* gla_  = sc + OFF_GLA;
    float* up_   = sc + OFF_UP;
    float* x2_   = qkvg_;

    __nv_bfloat16* actHi = act;
    __nv_bfloat16* actLo = act + ACT_PLANE;
    __nv_bfloat16* upHi  = upa;
    __nv_bfloat16* upLo  = upa + UPA_PLANE;

    __nv_bfloat16* wQKVGhi = wb + OW_QKVG;
    __nv_bfloat16* wQKVGlo = wQKVGhi + 3145728ull;

    cudaFuncSetAttribute(gla_attn_kernel,
                         cudaFuncAttributeMaxDynamicSharedMemorySize, GLA_SMEM_BYTES);
    cudaFuncSetAttribute(hgemm_kernel<0>,
                         cudaFuncAttributeMaxDynamicSharedMemorySize, HG_SMEM);
    cudaFuncSetAttribute(hgemm_kernel<1>,
                         cudaFuncAttributeMaxDynamicSharedMemorySize, HG_SMEM);
    cudaFuncSetAttribute(hgemm_kernel<2>,
                         cudaFuncAttributeMaxDynamicSharedMemorySize, HG_SMEM);

    dim3 tb(32, 8);
    wconv_kernel<<<dim3(HS/32, DKTOT/32), tb>>>(Wq, wQKVGhi,              wQKVGlo,              HS, DKTOT);
    wconv_kernel<<<dim3(HS/32, DKTOT/32), tb>>>(Wk, wQKVGhi +  512ull*HS, wQKVGlo +  512ull*HS, HS, DKTOT);
    wconv_kernel<<<dim3(HS/32, DVTOT/32), tb>>>(Wv, wQKVGhi + 1024ull*HS, wQKVGlo + 1024ull*HS, HS, DVTOT);
    wconv_kernel<<<dim3(HS/32, DVTOT/32), tb>>>(Wg, wQKVGhi + 2048ull*HS, wQKVGlo + 2048ull*HS, HS, DVTOT);
    wconv_kernel<<<dim3(DVTOT/32, HS/32), tb>>>(Wo,     wb + OW_O,    wb + OW_O    + 1048576, DVTOT, HS);
    wconv_kernel<<<dim3(HS/32, IMLP/32),  tb>>>(W_gate, wb + OW_GATE, wb + OW_GATE + 2883584, HS,   IMLP);
    wconv_kernel<<<dim3(HS/32, IMLP/32),  tb>>>(W_up,   wb + OW_UPW,  wb + OW_UPW  + 2883584, HS,   IMLP);
    wconv_kernel<<<dim3(IMLP/32, HS/32),  tb>>>(W_down, wb + OW_DOWN, wb + OW_DOWN + 2883584, IMLP, HS);

    // 1. h = rms(x)
    rmsnorm1024_kernel<<<NTOK, 256>>>(x, attn_w, h_, actHi, actLo);

    // 2. fused QKVG projection (N=3072)
    hgemm_kernel<0><<<dim3(QS/128, NTOK/128), 256, HG_SMEM>>>(
        actHi, actLo, wQKVGhi, wQKVGlo, qkvg_, nullptr, nullptr, nullptr, QS, HS);

    // 3. low-rank gate logits
    glow_kernel<<<(NTOK * RLOW) / 256, 256>>>(h_, Wgk1, glow_);
    glog_kernel<<<(NTOK * DKTOT) / 256, 256>>>(glow_, Wgk2, bgk2, glog_);

    // 4. chunked GLA (8-way dv split, 128 CTAs)
    gla_attn_kernel<<<dim3(8, NH, 4), 256, GLA_SMEM_BYTES>>>(qkvg_, glog_, gla_);

    // 5. per-head rmsnorm + swish gate -> og planes
    gnorm_gate_kernel<<<NTOK * NH, 256>>>(gla_, qkvg_, gnorm_w, actHi, actLo);

    // 6. x2 = og@Wo + x
    hgemm_kernel<1><<<dim3(HS/128, NTOK/128), 256, HG_SMEM>>>(
        actHi, actLo, wb + OW_O, wb + OW_O + 1048576, x2_, x, nullptr, nullptr, HS, DVTOT);

    // 7. mlp norm -> n planes
    rmsnorm1024_kernel<<<NTOK, 256>>>(x2_, mlp_w, nullptr, actHi, actLo);

    // 8. SwiGLU
    hgemm_kernel<0><<<dim3(IMLP/128, NTOK/128), 256, HG_SMEM>>>(
        actHi, actLo, wb + OW_UPW, wb + OW_UPW + 2883584, up_, nullptr, nullptr, nullptr, IMLP, HS);
    hgemm_kernel<2><<<dim3(IMLP/128, NTOK/128), 256, HG_SMEM>>>(
        actHi, actLo, wb + OW_GATE, wb + OW_GATE + 2883584, nullptr, up_, upHi, upLo, IMLP, HS);

    // 9. out = up@W_down + x2
    hgemm_kernel<1><<<dim3(HS/128, NTOK/128), 256, HG_SMEM>>>(
        upHi, upLo, wb + OW_DOWN, wb + OW_DOWN + 2883584, out, x2_, nullptr, nullptr, HS, IMLP);
}